// round 1
// baseline (speedup 1.0000x reference)
#include <cuda_runtime.h>
#include <cuda_bf16.h>
#include <cstdint>

// Shapes (fixed by the problem)
#define S_LEN 2048
#define DIM   5120
#define NH    40
#define DH    128
#define N3    15360   // 3*DIM

// Scratch (device globals: no allocation allowed in kernel_launch)
__device__ float g_qkv[(size_t)S_LEN * N3];        // 2048 x 15360
__device__ float g_attn_out[(size_t)S_LEN * DIM];  // 2048 x 5120

// ---------------------------------------------------------------------------
// SGEMM: C[M,N] = A[M,K] @ B[K,N] + bias[N]   (all row-major fp32)
// 128x128 block tile, BK=16, 256 threads, 8x8 per-thread microtile.
// ---------------------------------------------------------------------------
__global__ __launch_bounds__(256)
void sgemm_bias_kernel(const float* __restrict__ A, const float* __restrict__ B,
                       const float* __restrict__ bias, float* __restrict__ C,
                       int M, int N, int K)
{
    __shared__ float As[16][128];  // [k][m] transposed
    __shared__ float Bs[16][128];  // [k][n]

    const int tid = threadIdx.x;
    const int tr = tid >> 4;       // 0..15
    const int tc = tid & 15;       // 0..15
    const int row0 = blockIdx.y * 128;
    const int col0 = blockIdx.x * 128;

    const float* Ab = A + (size_t)row0 * K;
    const float* Bb = B + col0;

    float acc[8][8];
#pragma unroll
    for (int i = 0; i < 8; i++)
#pragma unroll
        for (int j = 0; j < 8; j++) acc[i][j] = 0.f;

    for (int k0 = 0; k0 < K; k0 += 16) {
        // Load A tile (128 rows x 16 cols) = 512 float4; 2 per thread.
#pragma unroll
        for (int i = 0; i < 2; i++) {
            int f = tid + i * 256;
            int arow = f >> 2, ac4 = f & 3;
            float4 v = *(const float4*)(Ab + (size_t)arow * K + k0 + ac4 * 4);
            As[ac4 * 4 + 0][arow] = v.x;
            As[ac4 * 4 + 1][arow] = v.y;
            As[ac4 * 4 + 2][arow] = v.z;
            As[ac4 * 4 + 3][arow] = v.w;
        }
        // Load B tile (16 rows x 128 cols) = 512 float4; 2 per thread.
#pragma unroll
        for (int i = 0; i < 2; i++) {
            int f = tid + i * 256;
            int brow = f >> 5, bc4 = f & 31;
            *(float4*)(&Bs[brow][bc4 * 4]) =
                *(const float4*)(Bb + (size_t)(k0 + brow) * N + bc4 * 4);
        }
        __syncthreads();

#pragma unroll
        for (int kk = 0; kk < 16; kk++) {
            float a[8], b[8];
            *(float4*)(a)     = *(const float4*)&As[kk][tr * 8];
            *(float4*)(a + 4) = *(const float4*)&As[kk][tr * 8 + 4];
            *(float4*)(b)     = *(const float4*)&Bs[kk][tc * 8];
            *(float4*)(b + 4) = *(const float4*)&Bs[kk][tc * 8 + 4];
#pragma unroll
            for (int i = 0; i < 8; i++)
#pragma unroll
                for (int j = 0; j < 8; j++)
                    acc[i][j] += a[i] * b[j];
        }
        __syncthreads();
    }

    // Epilogue: add bias, write out.
#pragma unroll
    for (int i = 0; i < 8; i++) {
        int row = row0 + tr * 8 + i;
        float* cp = C + (size_t)row * N + col0 + tc * 8;
#pragma unroll
        for (int j = 0; j < 8; j++)
            cp[j] = acc[i][j] + bias[col0 + tc * 8 + j];
    }
}

// ---------------------------------------------------------------------------
// Fused RMSNorm(q) + RMSNorm(k) + RoPE(q) + RoPE(k), in place on g_qkv.
// One block per token. Variance is over the full DIM=5120 (per reference).
// ---------------------------------------------------------------------------
__global__ __launch_bounds__(256)
void rmsnorm_rope_kernel(float* __restrict__ qkv,
                         const float* __restrict__ cos_t,
                         const float* __restrict__ sin_t,
                         const float* __restrict__ wq,
                         const float* __restrict__ wk)
{
    const int s = blockIdx.x;
    float* q = qkv + (size_t)s * N3;
    float* k = q + DIM;

    float sq = 0.f, sk = 0.f;
    for (int i = threadIdx.x; i < DIM; i += blockDim.x) {
        float a = q[i]; sq += a * a;
        float b = k[i]; sk += b * b;
    }
#pragma unroll
    for (int o = 16; o; o >>= 1) {
        sq += __shfl_xor_sync(0xffffffffu, sq, o);
        sk += __shfl_xor_sync(0xffffffffu, sk, o);
    }
    __shared__ float red[2][32];
    const int wid = threadIdx.x >> 5, lid = threadIdx.x & 31;
    if (lid == 0) { red[0][wid] = sq; red[1][wid] = sk; }
    __syncthreads();
    if (threadIdx.x == 0) {
        float a = 0.f, b = 0.f;
        const int nw = blockDim.x >> 5;
        for (int i = 0; i < nw; i++) { a += red[0][i]; b += red[1][i]; }
        red[0][0] = a; red[1][0] = b;
    }
    __syncthreads();
    const float rq = rsqrtf(red[0][0] / (float)DIM + 1e-6f);
    const float rk = rsqrtf(red[1][0] / (float)DIM + 1e-6f);

    // 2560 (even,odd) pairs per token; pair-in-head i = p % 64.
    for (int p = threadIdx.x; p < DIM / 2; p += blockDim.x) {
        const int e = 2 * p, o = 2 * p + 1;
        const int ih = p & 63;
        const float ce = cos_t[s * DH + 2 * ih];
        const float so = sin_t[s * DH + 2 * ih + 1];

        float qe = q[e] * rq * wq[e], qo = q[o] * rq * wq[o];
        q[e] = qe * ce - qo * so;
        q[o] = qe * so + qo * ce;

        float ke = k[e] * rk * wk[e], ko = k[o] * rk * wk[o];
        k[e] = ke * ce - ko * so;
        k[o] = ke * so + ko * ce;
    }
}

// ---------------------------------------------------------------------------
// Flash attention (fp32, online softmax). Grid (32 qblocks, 40 heads).
// 256 threads: thread t owns query-row r = t/4; quad = t%4 covers
// 16 score columns (S pass) and 32 output dims (PV pass).
// ---------------------------------------------------------------------------
#define BQ 64
#define BKT 64
#define TPITCH 132   // 128 + 4 pad
#define PPITCH 68    // 64 + 4 pad
#define ATTN_SMEM ((3 * BQ * TPITCH + BQ * PPITCH) * (int)sizeof(float))

__global__ __launch_bounds__(256)
void attn_kernel(const float* __restrict__ qkv, float* __restrict__ out)
{
    extern __shared__ float sm[];
    float* Qs = sm;                    // 64 x 132
    float* Ks = Qs + BQ * TPITCH;      // 64 x 132
    float* Vs = Ks + BKT * TPITCH;     // 64 x 132
    float* Ps = Vs + BKT * TPITCH;     // 64 x 68

    const int qb = blockIdx.x;   // 0..31
    const int h  = blockIdx.y;   // 0..39
    const int tid = threadIdx.x;
    const int r    = tid >> 2;   // 0..63
    const int quad = tid & 3;    // 0..3
    const int c0 = quad * 16;
    const int d0 = quad * 32;

    // Stage Q tile
    const float* Qg = qkv + (size_t)(qb * BQ) * N3 + h * DH;
    for (int f = tid; f < BQ * 32; f += 256) {
        int row = f >> 5, c4 = f & 31;
        float4 v = *(const float4*)(Qg + (size_t)row * N3 + c4 * 4);
        float* dst = Qs + row * TPITCH + c4 * 4;
        dst[0] = v.x; dst[1] = v.y; dst[2] = v.z; dst[3] = v.w;
    }

    float O[32];
#pragma unroll
    for (int i = 0; i < 32; i++) O[i] = 0.f;
    float m_run = -1e30f, l_run = 0.f;
    const float scale = 0.08838834764831845f;  // 128^-0.5

    for (int kt = 0; kt < S_LEN / BKT; kt++) {
        __syncthreads();  // prior-iter smem consumers done (also guards Qs on iter 0)
        const float* Kg = qkv + (size_t)(kt * BKT) * N3 + DIM + h * DH;
        const float* Vg = qkv + (size_t)(kt * BKT) * N3 + 2 * DIM + h * DH;
        for (int f = tid; f < BKT * 32; f += 256) {
            int row = f >> 5, c4 = f & 31;
            float4 kv = *(const float4*)(Kg + (size_t)row * N3 + c4 * 4);
            float4 vv = *(const float4*)(Vg + (size_t)row * N3 + c4 * 4);
            float* dk = Ks + row * TPITCH + c4 * 4;
            dk[0] = kv.x; dk[1] = kv.y; dk[2] = kv.z; dk[3] = kv.w;
            float* dv = Vs + row * TPITCH + c4 * 4;
            dv[0] = vv.x; dv[1] = vv.y; dv[2] = vv.z; dv[3] = vv.w;
        }
        __syncthreads();

        // S[r][c0..c0+16] = Q[r] . K[c]
        float sacc[16];
#pragma unroll
        for (int i = 0; i < 16; i++) sacc[i] = 0.f;
        for (int k4 = 0; k4 < DH / 4; k4++) {
            float4 qv = *(const float4*)(Qs + r * TPITCH + k4 * 4);
#pragma unroll
            for (int cc = 0; cc < 16; cc++) {
                float4 kv = *(const float4*)(Ks + (c0 + cc) * TPITCH + k4 * 4);
                sacc[cc] += qv.x * kv.x + qv.y * kv.y + qv.z * kv.z + qv.w * kv.w;
            }
        }

        // Online softmax (state replicated across the 4 threads of a row)
        float mt = -1e30f;
#pragma unroll
        for (int i = 0; i < 16; i++) { sacc[i] *= scale; mt = fmaxf(mt, sacc[i]); }
        mt = fmaxf(mt, __shfl_xor_sync(0xffffffffu, mt, 1));
        mt = fmaxf(mt, __shfl_xor_sync(0xffffffffu, mt, 2));
        const float m_new = fmaxf(m_run, mt);
        const float alpha = __expf(m_run - m_new);
        float lsum = 0.f;
#pragma unroll
        for (int i = 0; i < 16; i++) {
            float p = __expf(sacc[i] - m_new);
            Ps[r * PPITCH + c0 + i] = p;
            lsum += p;
        }
        lsum += __shfl_xor_sync(0xffffffffu, lsum, 1);
        lsum += __shfl_xor_sync(0xffffffffu, lsum, 2);
        l_run = l_run * alpha + lsum;
        m_run = m_new;
#pragma unroll
        for (int i = 0; i < 32; i++) O[i] *= alpha;
        __syncthreads();

        // O[r][d0..d0+32] += P[r][:] @ V[:][d]
        for (int j = 0; j < BKT; j++) {
            const float p = Ps[r * PPITCH + j];
            const float* vrow = Vs + j * TPITCH + d0;
#pragma unroll
            for (int dd = 0; dd < 8; dd++) {
                float4 vv = *(const float4*)(vrow + dd * 4);
                O[dd * 4 + 0] += p * vv.x;
                O[dd * 4 + 1] += p * vv.y;
                O[dd * 4 + 2] += p * vv.z;
                O[dd * 4 + 3] += p * vv.w;
            }
        }
    }

    const float inv = 1.f / l_run;
    float* og = out + (size_t)(qb * BQ + r) * DIM + h * DH + d0;
#pragma unroll
    for (int i = 0; i < 32; i++) og[i] = O[i] * inv;
}

// ---------------------------------------------------------------------------
// Launch
// ---------------------------------------------------------------------------
extern "C" void kernel_launch(void* const* d_in, const int* in_sizes, int n_in,
                              void* d_out, int out_size)
{
    const float* hidden = (const float*)d_in[0];
    const float* cos_t  = (const float*)d_in[1];
    const float* sin_t  = (const float*)d_in[2];
    const float* w_qkv  = (const float*)d_in[3];
    const float* b_qkv  = (const float*)d_in[4];
    const float* w_qn   = (const float*)d_in[5];
    const float* w_kn   = (const float*)d_in[6];
    const float* w_out  = (const float*)d_in[7];
    const float* b_out  = (const float*)d_in[8];
    float* out = (float*)d_out;

    float *qkv = nullptr, *attn = nullptr;
    cudaGetSymbolAddress((void**)&qkv, g_qkv);
    cudaGetSymbolAddress((void**)&attn, g_attn_out);

    cudaFuncSetAttribute(attn_kernel, cudaFuncAttributeMaxDynamicSharedMemorySize,
                         ATTN_SMEM);

    // 1) QKV = X @ Wqkv + b
    sgemm_bias_kernel<<<dim3(N3 / 128, S_LEN / 128), 256>>>(
        hidden, w_qkv, b_qkv, qkv, S_LEN, N3, DIM);

    // 2) RMSNorm(q), RMSNorm(k), RoPE both — in place
    rmsnorm_rope_kernel<<<S_LEN, 256>>>(qkv, cos_t, sin_t, w_qn, w_kn);

    // 3) Attention per head (flash, online softmax)
    attn_kernel<<<dim3(S_LEN / BQ, NH), 256, ATTN_SMEM>>>(qkv, attn);

    // 4) out = attn_out @ Wout + b
    sgemm_bias_kernel<<<dim3(DIM / 128, S_LEN / 128), 256>>>(
        attn, w_out, b_out, out, S_LEN, DIM, DIM);
}

// round 3
// speedup vs baseline: 1.2712x; 1.2712x over previous
#include <cuda_runtime.h>
#include <cuda_bf16.h>
#include <cstdint>

// Shapes (fixed by the problem)
#define S_LEN 2048
#define DIM   5120
#define NH    40
#define DH    128
#define N3    15360   // 3*DIM

// ---------------------------------------------------------------------------
// Scratch (device globals: no allocation allowed in kernel_launch)
// ---------------------------------------------------------------------------
__device__ float g_qkv[(size_t)S_LEN * N3];        // 2048 x 15360
__device__ float g_attn_out[(size_t)S_LEN * DIM];  // 2048 x 5120
// bf16 hi/lo split operands for tensor-core GEMMs
__device__ __nv_bfloat16 g_Ah[(size_t)S_LEN * DIM];     // activations hi  [M][K]
__device__ __nv_bfloat16 g_Al[(size_t)S_LEN * DIM];     // activations lo
__device__ __nv_bfloat16 g_Wqkv_h[(size_t)N3 * DIM];    // w_qkv^T hi [N][K]
__device__ __nv_bfloat16 g_Wqkv_l[(size_t)N3 * DIM];
__device__ __nv_bfloat16 g_Wout_h[(size_t)DIM * DIM];   // w_out^T hi [N][K]
__device__ __nv_bfloat16 g_Wout_l[(size_t)DIM * DIM];

// ---------------------------------------------------------------------------
// Baseline-PTX helpers (work on sm_103 family target: no 'a' features)
// ---------------------------------------------------------------------------
__device__ __forceinline__ uint32_t smem_u32(const void* p) {
    uint32_t a;
    asm("{ .reg .u64 t; cvta.to.shared.u64 t, %1; cvt.u32.u64 %0, t; }"
        : "=r"(a) : "l"(p));
    return a;
}

#define CP_ASYNC16(dst, src) \
    asm volatile("cp.async.cg.shared.global [%0], [%1], 16;" \
        :: "r"(dst), "l"(src) : "memory")
#define CP_COMMIT() asm volatile("cp.async.commit_group;" ::: "memory")
#define CP_WAIT0()  asm volatile("cp.async.wait_group 0;" ::: "memory")
#define CP_WAIT1()  asm volatile("cp.async.wait_group 1;" ::: "memory")

#define LDMATRIX_X4(r0, r1, r2, r3, addr) \
    asm volatile("ldmatrix.sync.aligned.m8n8.x4.shared.b16 {%0,%1,%2,%3}, [%4];" \
        : "=r"(r0), "=r"(r1), "=r"(r2), "=r"(r3) : "r"(addr))

#define MMA_BF16(d, a, b) \
    asm volatile( \
        "mma.sync.aligned.m16n8k16.row.col.f32.bf16.bf16.f32 " \
        "{%0,%1,%2,%3}, {%4,%5,%6,%7}, {%8,%9}, {%0,%1,%2,%3};" \
        : "+f"((d)[0]), "+f"((d)[1]), "+f"((d)[2]), "+f"((d)[3]) \
        : "r"((a)[0]), "r"((a)[1]), "r"((a)[2]), "r"((a)[3]), \
          "r"((b)[0]), "r"((b)[1]))

// ---------------------------------------------------------------------------
// Prepass 1: elementwise fp32 -> (bf16 hi, bf16 lo), same layout.
// ---------------------------------------------------------------------------
__global__ __launch_bounds__(256)
void split_rows(const float* __restrict__ X, __nv_bfloat16* __restrict__ H,
                __nv_bfloat16* __restrict__ L)
{
    size_t i = ((size_t)blockIdx.x * 256 + threadIdx.x) * 4;
    float4 v = *reinterpret_cast<const float4*>(X + i);
    __nv_bfloat16 h0 = __float2bfloat16(v.x), h1 = __float2bfloat16(v.y);
    __nv_bfloat16 h2 = __float2bfloat16(v.z), h3 = __float2bfloat16(v.w);
    __nv_bfloat16 l0 = __float2bfloat16(v.x - __bfloat162float(h0));
    __nv_bfloat16 l1 = __float2bfloat16(v.y - __bfloat162float(h1));
    __nv_bfloat16 l2 = __float2bfloat16(v.z - __bfloat162float(h2));
    __nv_bfloat16 l3 = __float2bfloat16(v.w - __bfloat162float(h3));
    __nv_bfloat162* Hp = reinterpret_cast<__nv_bfloat162*>(H + i);
    __nv_bfloat162* Lp = reinterpret_cast<__nv_bfloat162*>(L + i);
    Hp[0] = __nv_bfloat162(h0, h1); Hp[1] = __nv_bfloat162(h2, h3);
    Lp[0] = __nv_bfloat162(l0, l1); Lp[1] = __nv_bfloat162(l2, l3);
}

// ---------------------------------------------------------------------------
// Prepass 2: W[K][N] fp32 -> T_hi/T_lo [N][K] bf16 (transpose + split)
// ---------------------------------------------------------------------------
__global__ __launch_bounds__(256)
void transpose_split(const float* __restrict__ W, __nv_bfloat16* __restrict__ Th,
                     __nv_bfloat16* __restrict__ Tl, int K, int N)
{
    __shared__ float t[32][33];
    const int k0 = blockIdx.x * 32, n0 = blockIdx.y * 32;
    const int tx = threadIdx.x & 31, ty = threadIdx.x >> 5;  // ty 0..7
#pragma unroll
    for (int i = 0; i < 4; i++)
        t[ty + i * 8][tx] = W[(size_t)(k0 + ty + i * 8) * N + n0 + tx];
    __syncthreads();
#pragma unroll
    for (int i = 0; i < 4; i++) {
        const int n = n0 + ty + i * 8;
        const float v = t[tx][ty + i * 8];
        __nv_bfloat16 h = __float2bfloat16(v);
        __nv_bfloat16 l = __float2bfloat16(v - __bfloat162float(h));
        Th[(size_t)n * K + k0 + tx] = h;
        Tl[(size_t)n * K + k0 + tx] = l;
    }
}

// ---------------------------------------------------------------------------
// Tensor-core GEMM via mma.sync bf16 (hi/lo 3-term split, fp32 accum).
// C[M,N] = A[M,K] @ B[K,N] + bias.  A: [M][K] hi/lo.  B pre-transposed [N][K].
// CTA 128x128, BK=32, 8 warps (4m x 2n), warp tile 32x64, cp.async 2-stage.
// ---------------------------------------------------------------------------
#define BK        32
#define SPITCH    40                      // bf16 elems per smem row (80 B)
#define TILE_B    (128 * SPITCH * 2)      // 10240 B per operand tile
#define STAGE_B   (4 * TILE_B)            // Ah, Al, Bh, Bl
#define GEMM_SMEM (2 * STAGE_B)           // 81920 B

__global__ __launch_bounds__(256)
void gemm_tc(const __nv_bfloat16* __restrict__ Ah, const __nv_bfloat16* __restrict__ Al,
             const __nv_bfloat16* __restrict__ Bh, const __nv_bfloat16* __restrict__ Bl,
             const float* __restrict__ bias, float* __restrict__ C, int N)
{
    constexpr int K = DIM;            // 5120
    constexpr int NCHUNK = K / BK;    // 160

    extern __shared__ char dsm[];
    const uint32_t sbase = smem_u32(dsm);

    const int tid = threadIdx.x;
    const int wid = tid >> 5, lane = tid & 31;
    const int warp_m = wid & 3;       // 0..3 -> 32-row slice
    const int warp_n = wid >> 2;      // 0..1 -> 64-col slice
    const int row0 = blockIdx.x * 128;
    const int col0 = blockIdx.y * 128;

    const __nv_bfloat16* gA[4] = { Ah + (size_t)row0 * K, Al + (size_t)row0 * K,
                                   Bh + (size_t)col0 * K, Bl + (size_t)col0 * K };

    // ---- async stage loader: 4 tiles x 512 16B-granules, 8 per thread ----
    auto load_stage = [&](int stage, int koff) {
        const uint32_t sb = sbase + stage * STAGE_B;
#pragma unroll
        for (int t = 0; t < 4; ++t) {
#pragma unroll
            for (int g2 = 0; g2 < 2; ++g2) {
                const int g = tid + g2 * 256;       // 0..511
                const int row = g >> 2, c16 = g & 3;
                const __nv_bfloat16* src = gA[t] + (size_t)row * K + koff + c16 * 8;
                const uint32_t dst = sb + t * TILE_B + row * (SPITCH * 2) + c16 * 16;
                CP_ASYNC16(dst, src);
            }
        }
    };

    float acc[2][8][4];
#pragma unroll
    for (int i = 0; i < 2; i++)
#pragma unroll
        for (int j = 0; j < 8; j++)
#pragma unroll
            for (int v = 0; v < 4; v++) acc[i][j][v] = 0.f;

    load_stage(0, 0);
    CP_COMMIT();

    for (int c = 0; c < NCHUNK; ++c) {
        if (c + 1 < NCHUNK) {
            load_stage((c + 1) & 1, (c + 1) * BK);
            CP_COMMIT();
            CP_WAIT1();
        } else {
            CP_WAIT0();
        }
        __syncthreads();

        const uint32_t sb = sbase + (c & 1) * STAGE_B;
        const uint32_t sAh = sb, sAl = sb + TILE_B;
        const uint32_t sBh = sb + 2 * TILE_B, sBl = sb + 3 * TILE_B;

#pragma unroll
        for (int k16 = 0; k16 < 2; ++k16) {
            const uint32_t kb = k16 * 32;   // byte offset of this k16 within row

            // A fragments: 2 m16 frags, hi + lo
            uint32_t a_h[2][4], a_l[2][4];
#pragma unroll
            for (int mf = 0; mf < 2; ++mf) {
                const uint32_t ro = (warp_m * 32 + mf * 16 + (lane & 15)) * (SPITCH * 2)
                                    + ((lane >> 4) * 16) + kb;
                LDMATRIX_X4(a_h[mf][0], a_h[mf][1], a_h[mf][2], a_h[mf][3], sAh + ro);
                LDMATRIX_X4(a_l[mf][0], a_l[mf][1], a_l[mf][2], a_l[mf][3], sAl + ro);
            }
            // B fragments: 4 ldmatrix.x4 cover n=64 (16 n-rows each), hi + lo
            uint32_t b_h[4][4], b_l[4][4];
#pragma unroll
            for (int nf = 0; nf < 4; ++nf) {
                const uint32_t ro = (warp_n * 64 + nf * 16 + (lane & 7) + ((lane >> 4) << 3))
                                    * (SPITCH * 2) + (((lane >> 3) & 1) * 16) + kb;
                LDMATRIX_X4(b_h[nf][0], b_h[nf][1], b_h[nf][2], b_h[nf][3], sBh + ro);
                LDMATRIX_X4(b_l[nf][0], b_l[nf][1], b_l[nf][2], b_l[nf][3], sBl + ro);
            }
            // 3-term split MMA: hh + hl + lh, shared fp32 accumulators
#pragma unroll
            for (int mf = 0; mf < 2; ++mf)
#pragma unroll
                for (int nf = 0; nf < 4; ++nf)
#pragma unroll
                    for (int half = 0; half < 2; ++half) {
                        uint32_t bh2[2] = { b_h[nf][half * 2], b_h[nf][half * 2 + 1] };
                        uint32_t bl2[2] = { b_l[nf][half * 2], b_l[nf][half * 2 + 1] };
                        float* d = acc[mf][nf * 2 + half];
                        MMA_BF16(d, a_h[mf], bh2);
                        MMA_BF16(d, a_h[mf], bl2);
                        MMA_BF16(d, a_l[mf], bh2);
                    }
        }
        __syncthreads();
    }

    // ---- Epilogue: acc regs -> gmem with bias ----
#pragma unroll
    for (int mf = 0; mf < 2; ++mf) {
        const int r0 = row0 + warp_m * 32 + mf * 16 + (lane >> 2);
#pragma unroll
        for (int nf = 0; nf < 8; ++nf) {
            const int col = col0 + warp_n * 64 + nf * 8 + (lane & 3) * 2;
            const float b0 = bias[col], b1 = bias[col + 1];
            float* p0 = C + (size_t)r0 * N + col;
            float* p1 = C + (size_t)(r0 + 8) * N + col;
            *reinterpret_cast<float2*>(p0) =
                make_float2(acc[mf][nf][0] + b0, acc[mf][nf][1] + b1);
            *reinterpret_cast<float2*>(p1) =
                make_float2(acc[mf][nf][2] + b0, acc[mf][nf][3] + b1);
        }
    }
}

// ---------------------------------------------------------------------------
// Fused RMSNorm(q) + RMSNorm(k) + RoPE, in place on g_qkv. (unchanged)
// ---------------------------------------------------------------------------
__global__ __launch_bounds__(256)
void rmsnorm_rope_kernel(float* __restrict__ qkv,
                         const float* __restrict__ cos_t,
                         const float* __restrict__ sin_t,
                         const float* __restrict__ wq,
                         const float* __restrict__ wk)
{
    const int s = blockIdx.x;
    float* q = qkv + (size_t)s * N3;
    float* k = q + DIM;

    float sq = 0.f, sk = 0.f;
    for (int i = threadIdx.x; i < DIM; i += blockDim.x) {
        float a = q[i]; sq += a * a;
        float b = k[i]; sk += b * b;
    }
#pragma unroll
    for (int o = 16; o; o >>= 1) {
        sq += __shfl_xor_sync(0xffffffffu, sq, o);
        sk += __shfl_xor_sync(0xffffffffu, sk, o);
    }
    __shared__ float red[2][32];
    const int wid = threadIdx.x >> 5, lid = threadIdx.x & 31;
    if (lid == 0) { red[0][wid] = sq; red[1][wid] = sk; }
    __syncthreads();
    if (threadIdx.x == 0) {
        float a = 0.f, b = 0.f;
        const int nw = blockDim.x >> 5;
        for (int i = 0; i < nw; i++) { a += red[0][i]; b += red[1][i]; }
        red[0][0] = a; red[1][0] = b;
    }
    __syncthreads();
    const float rq = rsqrtf(red[0][0] / (float)DIM + 1e-6f);
    const float rk = rsqrtf(red[1][0] / (float)DIM + 1e-6f);

    for (int p = threadIdx.x; p < DIM / 2; p += blockDim.x) {
        const int e = 2 * p, o = 2 * p + 1;
        const int ih = p & 63;
        const float ce = cos_t[s * DH + 2 * ih];
        const float so = sin_t[s * DH + 2 * ih + 1];

        float qe = q[e] * rq * wq[e], qo = q[o] * rq * wq[o];
        q[e] = qe * ce - qo * so;
        q[o] = qe * so + qo * ce;

        float ke = k[e] * rk * wk[e], ko = k[o] * rk * wk[o];
        k[e] = ke * ce - ko * so;
        k[o] = ke * so + ko * ce;
    }
}

// ---------------------------------------------------------------------------
// Flash attention (fp32, online softmax). (unchanged from round 1)
// ---------------------------------------------------------------------------
#define BQ 64
#define BKT 64
#define TPITCH 132
#define PPITCH 68
#define ATTN_SMEM ((3 * BQ * TPITCH + BQ * PPITCH) * (int)sizeof(float))

__global__ __launch_bounds__(256)
void attn_kernel(const float* __restrict__ qkv, float* __restrict__ out)
{
    extern __shared__ float smf[];
    float* Qs = smf;
    float* Ks = Qs + BQ * TPITCH;
    float* Vs = Ks + BKT * TPITCH;
    float* Ps = Vs + BKT * TPITCH;

    const int qb = blockIdx.x;
    const int h  = blockIdx.y;
    const int tid = threadIdx.x;
    const int r    = tid >> 2;
    const int quad = tid & 3;
    const int c0 = quad * 16;
    const int d0 = quad * 32;

    const float* Qg = qkv + (size_t)(qb * BQ) * N3 + h * DH;
    for (int f = tid; f < BQ * 32; f += 256) {
        int row = f >> 5, c4 = f & 31;
        float4 v = *(const float4*)(Qg + (size_t)row * N3 + c4 * 4);
        float* dst = Qs + row * TPITCH + c4 * 4;
        dst[0] = v.x; dst[1] = v.y; dst[2] = v.z; dst[3] = v.w;
    }

    float O[32];
#pragma unroll
    for (int i = 0; i < 32; i++) O[i] = 0.f;
    float m_run = -1e30f, l_run = 0.f;
    const float scale = 0.08838834764831845f;

    for (int kt = 0; kt < S_LEN / BKT; kt++) {
        __syncthreads();
        const float* Kg = qkv + (size_t)(kt * BKT) * N3 + DIM + h * DH;
        const float* Vg = qkv + (size_t)(kt * BKT) * N3 + 2 * DIM + h * DH;
        for (int f = tid; f < BKT * 32; f += 256) {
            int row = f >> 5, c4 = f & 31;
            float4 kv = *(const float4*)(Kg + (size_t)row * N3 + c4 * 4);
            float4 vv = *(const float4*)(Vg + (size_t)row * N3 + c4 * 4);
            float* dk = Ks + row * TPITCH + c4 * 4;
            dk[0] = kv.x; dk[1] = kv.y; dk[2] = kv.z; dk[3] = kv.w;
            float* dv = Vs + row * TPITCH + c4 * 4;
            dv[0] = vv.x; dv[1] = vv.y; dv[2] = vv.z; dv[3] = vv.w;
        }
        __syncthreads();

        float sacc[16];
#pragma unroll
        for (int i = 0; i < 16; i++) sacc[i] = 0.f;
        for (int k4 = 0; k4 < DH / 4; k4++) {
            float4 qv = *(const float4*)(Qs + r * TPITCH + k4 * 4);
#pragma unroll
            for (int cc = 0; cc < 16; cc++) {
                float4 kv = *(const float4*)(Ks + (c0 + cc) * TPITCH + k4 * 4);
                sacc[cc] += qv.x * kv.x + qv.y * kv.y + qv.z * kv.z + qv.w * kv.w;
            }
        }

        float mt = -1e30f;
#pragma unroll
        for (int i = 0; i < 16; i++) { sacc[i] *= scale; mt = fmaxf(mt, sacc[i]); }
        mt = fmaxf(mt, __shfl_xor_sync(0xffffffffu, mt, 1));
        mt = fmaxf(mt, __shfl_xor_sync(0xffffffffu, mt, 2));
        const float m_new = fmaxf(m_run, mt);
        const float alpha = __expf(m_run - m_new);
        float lsum = 0.f;
#pragma unroll
        for (int i = 0; i < 16; i++) {
            float p = __expf(sacc[i] - m_new);
            Ps[r * PPITCH + c0 + i] = p;
            lsum += p;
        }
        lsum += __shfl_xor_sync(0xffffffffu, lsum, 1);
        lsum += __shfl_xor_sync(0xffffffffu, lsum, 2);
        l_run = l_run * alpha + lsum;
        m_run = m_new;
#pragma unroll
        for (int i = 0; i < 32; i++) O[i] *= alpha;
        __syncthreads();

        for (int j = 0; j < BKT; j++) {
            const float p = Ps[r * PPITCH + j];
            const float* vrow = Vs + j * TPITCH + d0;
#pragma unroll
            for (int dd = 0; dd < 8; dd++) {
                float4 vv = *(const float4*)(vrow + dd * 4);
                O[dd * 4 + 0] += p * vv.x;
                O[dd * 4 + 1] += p * vv.y;
                O[dd * 4 + 2] += p * vv.z;
                O[dd * 4 + 3] += p * vv.w;
            }
        }
    }

    const float inv = 1.f / l_run;
    float* og = out + (size_t)(qb * BQ + r) * DIM + h * DH + d0;
#pragma unroll
    for (int i = 0; i < 32; i++) og[i] = O[i] * inv;
}

// ---------------------------------------------------------------------------
// Launch
// ---------------------------------------------------------------------------
extern "C" void kernel_launch(void* const* d_in, const int* in_sizes, int n_in,
                              void* d_out, int out_size)
{
    const float* hidden = (const float*)d_in[0];
    const float* cos_t  = (const float*)d_in[1];
    const float* sin_t  = (const float*)d_in[2];
    const float* w_qkv  = (const float*)d_in[3];
    const float* b_qkv  = (const float*)d_in[4];
    const float* w_qn   = (const float*)d_in[5];
    const float* w_kn   = (const float*)d_in[6];
    const float* w_out  = (const float*)d_in[7];
    const float* b_out  = (const float*)d_in[8];
    float* out = (float*)d_out;

    float *qkv = nullptr, *attn = nullptr;
    __nv_bfloat16 *Ah, *Al, *Wqh, *Wql, *Woh, *Wol;
    cudaGetSymbolAddress((void**)&qkv, g_qkv);
    cudaGetSymbolAddress((void**)&attn, g_attn_out);
    cudaGetSymbolAddress((void**)&Ah, g_Ah);
    cudaGetSymbolAddress((void**)&Al, g_Al);
    cudaGetSymbolAddress((void**)&Wqh, g_Wqkv_h);
    cudaGetSymbolAddress((void**)&Wql, g_Wqkv_l);
    cudaGetSymbolAddress((void**)&Woh, g_Wout_h);
    cudaGetSymbolAddress((void**)&Wol, g_Wout_l);

    cudaFuncSetAttribute(attn_kernel, cudaFuncAttributeMaxDynamicSharedMemorySize,
                         ATTN_SMEM);
    cudaFuncSetAttribute(gemm_tc, cudaFuncAttributeMaxDynamicSharedMemorySize,
                         GEMM_SMEM);

    // Prepass: split/transpose operands to bf16 hi/lo
    transpose_split<<<dim3(DIM / 32, N3 / 32), 256>>>(w_qkv, Wqh, Wql, DIM, N3);
    transpose_split<<<dim3(DIM / 32, DIM / 32), 256>>>(w_out, Woh, Wol, DIM, DIM);
    split_rows<<<(S_LEN * DIM) / 1024, 256>>>(hidden, Ah, Al);

    // 1) QKV = X @ Wqkv + b   (mma.sync tensor cores)
    gemm_tc<<<dim3(S_LEN / 128, N3 / 128), 256, GEMM_SMEM>>>(
        Ah, Al, Wqh, Wql, b_qkv, qkv, N3);

    // 2) RMSNorm + RoPE
    rmsnorm_rope_kernel<<<S_LEN, 256>>>(qkv, cos_t, sin_t, w_qn, w_kn);

    // 3) Flash attention
    attn_kernel<<<dim3(S_LEN / BQ, NH), 256, ATTN_SMEM>>>(qkv, attn);

    // 4) out = attn_out @ Wout + b   (mma.sync tensor cores)
    split_rows<<<(S_LEN * DIM) / 1024, 256>>>(attn, Ah, Al);
    gemm_tc<<<dim3(S_LEN / 128, DIM / 128), 256, GEMM_SMEM>>>(
        Ah, Al, Woh, Wol, b_out, out, DIM);
}

// round 4
// speedup vs baseline: 6.3152x; 4.9680x over previous
#include <cuda_runtime.h>
#include <cuda_bf16.h>
#include <cstdint>

// Shapes (fixed by the problem)
#define S_LEN 2048
#define DIM   5120
#define NH    40
#define DH    128
#define N3    15360   // 3*DIM

// ---------------------------------------------------------------------------
// Scratch (device globals: no allocation allowed in kernel_launch)
// ---------------------------------------------------------------------------
__device__ float g_qkv[(size_t)S_LEN * N3];        // 2048 x 15360 (QKV GEMM out)
__device__ float g_attn_out[(size_t)S_LEN * DIM];  // 2048 x 5120
__device__ __nv_bfloat16 g_Ah[(size_t)S_LEN * DIM];     // activations hi  [M][K]
__device__ __nv_bfloat16 g_Al[(size_t)S_LEN * DIM];     // activations lo
__device__ __nv_bfloat16 g_Wqkv_h[(size_t)N3 * DIM];    // w_qkv^T hi [N][K]
__device__ __nv_bfloat16 g_Wqkv_l[(size_t)N3 * DIM];
__device__ __nv_bfloat16 g_Wout_h[(size_t)DIM * DIM];   // w_out^T hi [N][K]
__device__ __nv_bfloat16 g_Wout_l[(size_t)DIM * DIM];
// bf16 hi/lo q/k (post norm+rope) and v for tensor-core attention, [s][DIM]
__device__ __nv_bfloat16 g_Qh[(size_t)S_LEN * DIM];
__device__ __nv_bfloat16 g_Ql[(size_t)S_LEN * DIM];
__device__ __nv_bfloat16 g_Kh[(size_t)S_LEN * DIM];
__device__ __nv_bfloat16 g_Kl[(size_t)S_LEN * DIM];
__device__ __nv_bfloat16 g_Vh[(size_t)S_LEN * DIM];
__device__ __nv_bfloat16 g_Vl[(size_t)S_LEN * DIM];

// ---------------------------------------------------------------------------
// Baseline-PTX helpers (sm_103 family target: no 'a' features)
// ---------------------------------------------------------------------------
__device__ __forceinline__ uint32_t smem_u32(const void* p) {
    uint32_t a;
    asm("{ .reg .u64 t; cvta.to.shared.u64 t, %1; cvt.u32.u64 %0, t; }"
        : "=r"(a) : "l"(p));
    return a;
}

#define CP_ASYNC16(dst, src) \
    asm volatile("cp.async.cg.shared.global [%0], [%1], 16;" \
        :: "r"(dst), "l"(src) : "memory")
#define CP_COMMIT() asm volatile("cp.async.commit_group;" ::: "memory")
#define CP_WAIT0()  asm volatile("cp.async.wait_group 0;" ::: "memory")
#define CP_WAIT1()  asm volatile("cp.async.wait_group 1;" ::: "memory")

#define LDMATRIX_X4(r0, r1, r2, r3, addr) \
    asm volatile("ldmatrix.sync.aligned.m8n8.x4.shared.b16 {%0,%1,%2,%3}, [%4];" \
        : "=r"(r0), "=r"(r1), "=r"(r2), "=r"(r3) : "r"(addr))
#define LDMATRIX_X4_T(r0, r1, r2, r3, addr) \
    asm volatile("ldmatrix.sync.aligned.m8n8.x4.trans.shared.b16 {%0,%1,%2,%3}, [%4];" \
        : "=r"(r0), "=r"(r1), "=r"(r2), "=r"(r3) : "r"(addr))

#define MMA_BF16(d, a, b) \
    asm volatile( \
        "mma.sync.aligned.m16n8k16.row.col.f32.bf16.bf16.f32 " \
        "{%0,%1,%2,%3}, {%4,%5,%6,%7}, {%8,%9}, {%0,%1,%2,%3};" \
        : "+f"((d)[0]), "+f"((d)[1]), "+f"((d)[2]), "+f"((d)[3]) \
        : "r"((a)[0]), "r"((a)[1]), "r"((a)[2]), "r"((a)[3]), \
          "r"((b)[0]), "r"((b)[1]))

// fp32 pair -> packed bf16x2 hi + residual lo
__device__ __forceinline__ void split2(float a, float b, uint32_t& hi, uint32_t& lo) {
    __nv_bfloat16 ha = __float2bfloat16(a), hb = __float2bfloat16(b);
    __nv_bfloat162 h2(ha, hb);
    __nv_bfloat162 l2(__float2bfloat16(a - __bfloat162float(ha)),
                      __float2bfloat16(b - __bfloat162float(hb)));
    hi = *reinterpret_cast<uint32_t*>(&h2);
    lo = *reinterpret_cast<uint32_t*>(&l2);
}

// ---------------------------------------------------------------------------
// Prepass 1: elementwise fp32 -> (bf16 hi, bf16 lo), same layout.
// ---------------------------------------------------------------------------
__global__ __launch_bounds__(256)
void split_rows(const float* __restrict__ X, __nv_bfloat16* __restrict__ H,
                __nv_bfloat16* __restrict__ L)
{
    size_t i = ((size_t)blockIdx.x * 256 + threadIdx.x) * 4;
    float4 v = *reinterpret_cast<const float4*>(X + i);
    uint32_t h0, l0, h1, l1;
    split2(v.x, v.y, h0, l0);
    split2(v.z, v.w, h1, l1);
    uint32_t* Hp = reinterpret_cast<uint32_t*>(H + i);
    uint32_t* Lp = reinterpret_cast<uint32_t*>(L + i);
    Hp[0] = h0; Hp[1] = h1;
    Lp[0] = l0; Lp[1] = l1;
}

// ---------------------------------------------------------------------------
// Prepass 2: W[K][N] fp32 -> T_hi/T_lo [N][K] bf16 (transpose + split)
// ---------------------------------------------------------------------------
__global__ __launch_bounds__(256)
void transpose_split(const float* __restrict__ W, __nv_bfloat16* __restrict__ Th,
                     __nv_bfloat16* __restrict__ Tl, int K, int N)
{
    __shared__ float t[32][33];
    const int k0 = blockIdx.x * 32, n0 = blockIdx.y * 32;
    const int tx = threadIdx.x & 31, ty = threadIdx.x >> 5;
#pragma unroll
    for (int i = 0; i < 4; i++)
        t[ty + i * 8][tx] = W[(size_t)(k0 + ty + i * 8) * N + n0 + tx];
    __syncthreads();
#pragma unroll
    for (int i = 0; i < 4; i++) {
        const int n = n0 + ty + i * 8;
        const float v = t[tx][ty + i * 8];
        __nv_bfloat16 h = __float2bfloat16(v);
        __nv_bfloat16 l = __float2bfloat16(v - __bfloat162float(h));
        Th[(size_t)n * K + k0 + tx] = h;
        Tl[(size_t)n * K + k0 + tx] = l;
    }
}

// ---------------------------------------------------------------------------
// Tensor-core GEMM via mma.sync bf16 (hi/lo 3-term split, fp32 accum).
// (unchanged from round 3 — validated)
// ---------------------------------------------------------------------------
#define BK        32
#define SPITCH    40
#define TILE_B    (128 * SPITCH * 2)
#define STAGE_B   (4 * TILE_B)
#define GEMM_SMEM (2 * STAGE_B)

__global__ __launch_bounds__(256)
void gemm_tc(const __nv_bfloat16* __restrict__ Ah, const __nv_bfloat16* __restrict__ Al,
             const __nv_bfloat16* __restrict__ Bh, const __nv_bfloat16* __restrict__ Bl,
             const float* __restrict__ bias, float* __restrict__ C, int N)
{
    constexpr int K = DIM;
    constexpr int NCHUNK = K / BK;

    extern __shared__ char dsm[];
    const uint32_t sbase = smem_u32(dsm);

    const int tid = threadIdx.x;
    const int wid = tid >> 5, lane = tid & 31;
    const int warp_m = wid & 3;
    const int warp_n = wid >> 2;
    const int row0 = blockIdx.x * 128;
    const int col0 = blockIdx.y * 128;

    const __nv_bfloat16* gA[4] = { Ah + (size_t)row0 * K, Al + (size_t)row0 * K,
                                   Bh + (size_t)col0 * K, Bl + (size_t)col0 * K };

    auto load_stage = [&](int stage, int koff) {
        const uint32_t sb = sbase + stage * STAGE_B;
#pragma unroll
        for (int t = 0; t < 4; ++t) {
#pragma unroll
            for (int g2 = 0; g2 < 2; ++g2) {
                const int g = tid + g2 * 256;
                const int row = g >> 2, c16 = g & 3;
                const __nv_bfloat16* src = gA[t] + (size_t)row * K + koff + c16 * 8;
                const uint32_t dst = sb + t * TILE_B + row * (SPITCH * 2) + c16 * 16;
                CP_ASYNC16(dst, src);
            }
        }
    };

    float acc[2][8][4];
#pragma unroll
    for (int i = 0; i < 2; i++)
#pragma unroll
        for (int j = 0; j < 8; j++)
#pragma unroll
            for (int v = 0; v < 4; v++) acc[i][j][v] = 0.f;

    load_stage(0, 0);
    CP_COMMIT();

    for (int c = 0; c < NCHUNK; ++c) {
        if (c + 1 < NCHUNK) {
            load_stage((c + 1) & 1, (c + 1) * BK);
            CP_COMMIT();
            CP_WAIT1();
        } else {
            CP_WAIT0();
        }
        __syncthreads();

        const uint32_t sb = sbase + (c & 1) * STAGE_B;
        const uint32_t sAh = sb, sAl = sb + TILE_B;
        const uint32_t sBh = sb + 2 * TILE_B, sBl = sb + 3 * TILE_B;

#pragma unroll
        for (int k16 = 0; k16 < 2; ++k16) {
            const uint32_t kb = k16 * 32;

            uint32_t a_h[2][4], a_l[2][4];
#pragma unroll
            for (int mf = 0; mf < 2; ++mf) {
                const uint32_t ro = (warp_m * 32 + mf * 16 + (lane & 15)) * (SPITCH * 2)
                                    + ((lane >> 4) * 16) + kb;
                LDMATRIX_X4(a_h[mf][0], a_h[mf][1], a_h[mf][2], a_h[mf][3], sAh + ro);
                LDMATRIX_X4(a_l[mf][0], a_l[mf][1], a_l[mf][2], a_l[mf][3], sAl + ro);
            }
            uint32_t b_h[4][4], b_l[4][4];
#pragma unroll
            for (int nf = 0; nf < 4; ++nf) {
                const uint32_t ro = (warp_n * 64 + nf * 16 + (lane & 7) + ((lane >> 4) << 3))
                                    * (SPITCH * 2) + (((lane >> 3) & 1) * 16) + kb;
                LDMATRIX_X4(b_h[nf][0], b_h[nf][1], b_h[nf][2], b_h[nf][3], sBh + ro);
                LDMATRIX_X4(b_l[nf][0], b_l[nf][1], b_l[nf][2], b_l[nf][3], sBl + ro);
            }
#pragma unroll
            for (int mf = 0; mf < 2; ++mf)
#pragma unroll
                for (int nf = 0; nf < 4; ++nf)
#pragma unroll
                    for (int half = 0; half < 2; ++half) {
                        uint32_t bh2[2] = { b_h[nf][half * 2], b_h[nf][half * 2 + 1] };
                        uint32_t bl2[2] = { b_l[nf][half * 2], b_l[nf][half * 2 + 1] };
                        float* d = acc[mf][nf * 2 + half];
                        MMA_BF16(d, a_h[mf], bh2);
                        MMA_BF16(d, a_h[mf], bl2);
                        MMA_BF16(d, a_l[mf], bh2);
                    }
        }
        __syncthreads();
    }

#pragma unroll
    for (int mf = 0; mf < 2; ++mf) {
        const int r0 = row0 + warp_m * 32 + mf * 16 + (lane >> 2);
#pragma unroll
        for (int nf = 0; nf < 8; ++nf) {
            const int col = col0 + warp_n * 64 + nf * 8 + (lane & 3) * 2;
            const float b0 = bias[col], b1 = bias[col + 1];
            float* p0 = C + (size_t)r0 * N + col;
            float* p1 = C + (size_t)(r0 + 8) * N + col;
            *reinterpret_cast<float2*>(p0) =
                make_float2(acc[mf][nf][0] + b0, acc[mf][nf][1] + b1);
            *reinterpret_cast<float2*>(p1) =
                make_float2(acc[mf][nf][2] + b0, acc[mf][nf][3] + b1);
        }
    }
}

// ---------------------------------------------------------------------------
// Fused RMSNorm(q,k) + RoPE + hi/lo split of q,k,v -> bf16 buffers [s][DIM].
// One block per token.
// ---------------------------------------------------------------------------
__global__ __launch_bounds__(256)
void rmsnorm_rope_split(const float* __restrict__ qkv,
                        const float* __restrict__ cos_t,
                        const float* __restrict__ sin_t,
                        const float* __restrict__ wq,
                        const float* __restrict__ wk,
                        __nv_bfloat16* __restrict__ Qh, __nv_bfloat16* __restrict__ Ql,
                        __nv_bfloat16* __restrict__ Kh, __nv_bfloat16* __restrict__ Kl,
                        __nv_bfloat16* __restrict__ Vh, __nv_bfloat16* __restrict__ Vl)
{
    const int s = blockIdx.x;
    const float* q = qkv + (size_t)s * N3;
    const float* k = q + DIM;
    const float* v = k + DIM;

    float sq = 0.f, sk = 0.f;
    for (int i = threadIdx.x; i < DIM; i += blockDim.x) {
        float a = q[i]; sq += a * a;
        float b = k[i]; sk += b * b;
    }
#pragma unroll
    for (int o = 16; o; o >>= 1) {
        sq += __shfl_xor_sync(0xffffffffu, sq, o);
        sk += __shfl_xor_sync(0xffffffffu, sk, o);
    }
    __shared__ float red[2][32];
    const int wid = threadIdx.x >> 5, lid = threadIdx.x & 31;
    if (lid == 0) { red[0][wid] = sq; red[1][wid] = sk; }
    __syncthreads();
    if (threadIdx.x == 0) {
        float a = 0.f, b = 0.f;
        for (int i = 0; i < 8; i++) { a += red[0][i]; b += red[1][i]; }
        red[0][0] = a; red[1][0] = b;
    }
    __syncthreads();
    const float rq = rsqrtf(red[0][0] / (float)DIM + 1e-6f);
    const float rk = rsqrtf(red[1][0] / (float)DIM + 1e-6f);

    const size_t ob = (size_t)s * DIM;
    for (int p = threadIdx.x; p < DIM / 2; p += blockDim.x) {
        const int e = 2 * p, o = 2 * p + 1;
        const int ih = p & 63;
        const float ce = cos_t[s * DH + 2 * ih];
        const float so = sin_t[s * DH + 2 * ih + 1];

        float qe = q[e] * rq * wq[e], qo = q[o] * rq * wq[o];
        float ke = k[e] * rk * wk[e], ko = k[o] * rk * wk[o];
        uint32_t hi, lo;
        split2(qe * ce - qo * so, qe * so + qo * ce, hi, lo);
        *reinterpret_cast<uint32_t*>(Qh + ob + e) = hi;
        *reinterpret_cast<uint32_t*>(Ql + ob + e) = lo;
        split2(ke * ce - ko * so, ke * so + ko * ce, hi, lo);
        *reinterpret_cast<uint32_t*>(Kh + ob + e) = hi;
        *reinterpret_cast<uint32_t*>(Kl + ob + e) = lo;
        split2(v[e], v[o], hi, lo);
        *reinterpret_cast<uint32_t*>(Vh + ob + e) = hi;
        *reinterpret_cast<uint32_t*>(Vl + ob + e) = lo;
    }
}

// ---------------------------------------------------------------------------
// Tensor-core flash attention (mma.sync bf16 hi/lo, fp32 online softmax).
// CTA: 128 q-rows x 1 head. 8 warps, warp = m16 rows, full n. K-tiles of 64.
// ---------------------------------------------------------------------------
#define A_BK     64
#define A_PITCHB 272                         // bytes per smem row (128 bf16 + 8 pad)
#define A_QBYTES (128 * A_PITCHB)            // 34816 (per hi or lo)
#define A_KTILE  (A_BK * A_PITCHB)           // 17408
#define A_STAGE  (4 * A_KTILE)               // Kh,Kl,Vh,Vl = 69632
#define ATTN_SMEM (2 * A_QBYTES + 2 * A_STAGE)  // 208896

__global__ __launch_bounds__(256)
void attn_tc(const __nv_bfloat16* __restrict__ Qh, const __nv_bfloat16* __restrict__ Ql,
             const __nv_bfloat16* __restrict__ Kh, const __nv_bfloat16* __restrict__ Kl,
             const __nv_bfloat16* __restrict__ Vh, const __nv_bfloat16* __restrict__ Vl,
             float* __restrict__ out)
{
    extern __shared__ char dsm[];
    const uint32_t base = smem_u32(dsm);
    const uint32_t sQh = base, sQl = base + A_QBYTES;
    const uint32_t stage0 = base + 2 * A_QBYTES;

    const int qb = blockIdx.x;       // 0..15
    const int h  = blockIdx.y;       // 0..39
    const int tid = threadIdx.x;
    const int warp = tid >> 5, lane = tid & 31;

    const __nv_bfloat16* kvsrc[4] = { Kh, Kl, Vh, Vl };

    // Q tile load (rows qb*128.., cols h*128..): 2048 granules each hi/lo
    {
        const size_t qoff = (size_t)(qb * 128) * DIM + h * DH;
#pragma unroll
        for (int g = 0; g < 8; ++g) {
            const int idx = tid + g * 256;
            const int row = idx >> 4, c = idx & 15;
            const size_t so = qoff + (size_t)row * DIM + c * 8;
            CP_ASYNC16(sQh + row * A_PITCHB + c * 16, Qh + so);
            CP_ASYNC16(sQl + row * A_PITCHB + c * 16, Ql + so);
        }
    }
    auto load_kv = [&](uint32_t st, int kt) {
        const size_t koff = (size_t)(kt * A_BK) * DIM + h * DH;
#pragma unroll
        for (int g = 0; g < 16; ++g) {
            const int t = g >> 2;
            const int idx = tid + (g & 3) * 256;     // 0..1023
            const int row = idx >> 4, c = idx & 15;
            CP_ASYNC16(st + t * A_KTILE + row * A_PITCHB + c * 16,
                       kvsrc[t] + koff + (size_t)row * DIM + c * 8);
        }
    };

    load_kv(stage0, 0);
    CP_COMMIT();                 // G0: Q + KV tile 0
    load_kv(stage0 + A_STAGE, 1);
    CP_COMMIT();                 // G1: KV tile 1

    float O[16][4];
#pragma unroll
    for (int i = 0; i < 16; i++)
#pragma unroll
        for (int j = 0; j < 4; j++) O[i][j] = 0.f;
    float m_run[2] = { -1e30f, -1e30f };
    float l_run[2] = { 0.f, 0.f };
    const float scale = 0.08838834764831845f;   // 128^-0.5

    constexpr int NT = S_LEN / A_BK;   // 32

    for (int kt = 0; kt < NT; ++kt) {
        if (kt == NT - 1) { CP_WAIT0(); } else { CP_WAIT1(); }
        __syncthreads();

        const uint32_t st = stage0 + (kt & 1) * A_STAGE;
        const uint32_t sKh = st, sKl = st + A_KTILE;
        const uint32_t sVh = st + 2 * A_KTILE, sVl = st + 3 * A_KTILE;

        // ---- S = Q K^T (16 x 64 per warp), 3-term split ----
        float sacc[8][4];
#pragma unroll
        for (int i = 0; i < 8; i++)
#pragma unroll
            for (int j = 0; j < 4; j++) sacc[i][j] = 0.f;

#pragma unroll
        for (int ks = 0; ks < 8; ++ks) {
            const uint32_t kb = ks * 32;
            uint32_t aH[4], aL[4];
            const uint32_t aro = (warp * 16 + (lane & 15)) * A_PITCHB
                                 + ((lane >> 4) * 16) + kb;
            LDMATRIX_X4(aH[0], aH[1], aH[2], aH[3], sQh + aro);
            LDMATRIX_X4(aL[0], aL[1], aL[2], aL[3], sQl + aro);
#pragma unroll
            for (int nb = 0; nb < 4; ++nb) {
                uint32_t bH[4], bL[4];
                const uint32_t bro = (nb * 16 + (lane & 7) + ((lane >> 4) << 3))
                                     * A_PITCHB + (((lane >> 3) & 1) * 16) + kb;
                LDMATRIX_X4(bH[0], bH[1], bH[2], bH[3], sKh + bro);
                LDMATRIX_X4(bL[0], bL[1], bL[2], bL[3], sKl + bro);
#pragma unroll
                for (int half = 0; half < 2; ++half) {
                    uint32_t bh2[2] = { bH[half * 2], bH[half * 2 + 1] };
                    uint32_t bl2[2] = { bL[half * 2], bL[half * 2 + 1] };
                    float* d = sacc[nb * 2 + half];
                    MMA_BF16(d, aH, bh2);
                    MMA_BF16(d, aH, bl2);
                    MMA_BF16(d, aL, bh2);
                }
            }
        }

        // ---- online softmax (rows lane>>2 and lane>>2 + 8) ----
        float mt0 = -1e30f, mt1 = -1e30f;
#pragma unroll
        for (int f = 0; f < 8; ++f) {
            sacc[f][0] *= scale; sacc[f][1] *= scale;
            sacc[f][2] *= scale; sacc[f][3] *= scale;
            mt0 = fmaxf(mt0, fmaxf(sacc[f][0], sacc[f][1]));
            mt1 = fmaxf(mt1, fmaxf(sacc[f][2], sacc[f][3]));
        }
        mt0 = fmaxf(mt0, __shfl_xor_sync(0xffffffffu, mt0, 1));
        mt0 = fmaxf(mt0, __shfl_xor_sync(0xffffffffu, mt0, 2));
        mt1 = fmaxf(mt1, __shfl_xor_sync(0xffffffffu, mt1, 1));
        mt1 = fmaxf(mt1, __shfl_xor_sync(0xffffffffu, mt1, 2));
        const float mn0 = fmaxf(m_run[0], mt0), mn1 = fmaxf(m_run[1], mt1);
        const float al0 = __expf(m_run[0] - mn0), al1 = __expf(m_run[1] - mn1);
        m_run[0] = mn0; m_run[1] = mn1;

        float ls0 = 0.f, ls1 = 0.f;
#pragma unroll
        for (int f = 0; f < 8; ++f) {
            sacc[f][0] = __expf(sacc[f][0] - mn0);
            sacc[f][1] = __expf(sacc[f][1] - mn0);
            sacc[f][2] = __expf(sacc[f][2] - mn1);
            sacc[f][3] = __expf(sacc[f][3] - mn1);
            ls0 += sacc[f][0] + sacc[f][1];
            ls1 += sacc[f][2] + sacc[f][3];
        }
        ls0 += __shfl_xor_sync(0xffffffffu, ls0, 1);
        ls0 += __shfl_xor_sync(0xffffffffu, ls0, 2);
        ls1 += __shfl_xor_sync(0xffffffffu, ls1, 1);
        ls1 += __shfl_xor_sync(0xffffffffu, ls1, 2);
        l_run[0] = l_run[0] * al0 + ls0;
        l_run[1] = l_run[1] * al1 + ls1;

#pragma unroll
        for (int i = 0; i < 16; i++) {
            O[i][0] *= al0; O[i][1] *= al0;
            O[i][2] *= al1; O[i][3] *= al1;
        }

        // P accum-frags -> A-operand frags (hi/lo), k16 steps over 64 tokens
        uint32_t pH[4][4], pL[4][4];
#pragma unroll
        for (int j = 0; j < 4; ++j) {
            split2(sacc[2 * j][0],     sacc[2 * j][1],     pH[j][0], pL[j][0]);
            split2(sacc[2 * j][2],     sacc[2 * j][3],     pH[j][1], pL[j][1]);
            split2(sacc[2 * j + 1][0], sacc[2 * j + 1][1], pH[j][2], pL[j][2]);
            split2(sacc[2 * j + 1][2], sacc[2 * j + 1][3], pH[j][3], pL[j][3]);
        }

        // ---- O += P V  (V via ldmatrix.trans), 3-term split ----
#pragma unroll
        for (int ks = 0; ks < 4; ++ks) {
            const uint32_t krow = ks * 16 + (lane & 7) + (((lane >> 3) & 1) * 8);
#pragma unroll
            for (int nb = 0; nb < 8; ++nb) {
                const uint32_t ro = krow * A_PITCHB + nb * 32 + ((lane >> 4) * 16);
                uint32_t bH[4], bL[4];
                LDMATRIX_X4_T(bH[0], bH[1], bH[2], bH[3], sVh + ro);
                LDMATRIX_X4_T(bL[0], bL[1], bL[2], bL[3], sVl + ro);
#pragma unroll
                for (int half = 0; half < 2; ++half) {
                    uint32_t bh2[2] = { bH[half * 2], bH[half * 2 + 1] };
                    uint32_t bl2[2] = { bL[half * 2], bL[half * 2 + 1] };
                    float* d = O[nb * 2 + half];
                    MMA_BF16(d, pH[ks], bh2);
                    MMA_BF16(d, pH[ks], bl2);
                    MMA_BF16(d, pL[ks], bh2);
                }
            }
        }

        __syncthreads();
        if (kt + 2 < NT) {
            load_kv(stage0 + (kt & 1) * A_STAGE, kt + 2);
            CP_COMMIT();
        }
    }

    // ---- epilogue ----
    const float inv0 = 1.f / l_run[0], inv1 = 1.f / l_run[1];
    const int s0 = qb * 128 + warp * 16 + (lane >> 2);
#pragma unroll
    for (int nf = 0; nf < 16; ++nf) {
        const int col = h * DH + nf * 8 + (lane & 3) * 2;
        *reinterpret_cast<float2*>(out + (size_t)s0 * DIM + col) =
            make_float2(O[nf][0] * inv0, O[nf][1] * inv0);
        *reinterpret_cast<float2*>(out + (size_t)(s0 + 8) * DIM + col) =
            make_float2(O[nf][2] * inv1, O[nf][3] * inv1);
    }
}

// ---------------------------------------------------------------------------
// Launch
// ---------------------------------------------------------------------------
extern "C" void kernel_launch(void* const* d_in, const int* in_sizes, int n_in,
                              void* d_out, int out_size)
{
    const float* hidden = (const float*)d_in[0];
    const float* cos_t  = (const float*)d_in[1];
    const float* sin_t  = (const float*)d_in[2];
    const float* w_qkv  = (const float*)d_in[3];
    const float* b_qkv  = (const float*)d_in[4];
    const float* w_qn   = (const float*)d_in[5];
    const float* w_kn   = (const float*)d_in[6];
    const float* w_out  = (const float*)d_in[7];
    const float* b_out  = (const float*)d_in[8];
    float* out = (float*)d_out;

    float *qkv, *attn;
    __nv_bfloat16 *Ah, *Al, *Wqh, *Wql, *Woh, *Wol, *Qh, *Ql, *Kh, *Kl, *Vh, *Vl;
    cudaGetSymbolAddress((void**)&qkv, g_qkv);
    cudaGetSymbolAddress((void**)&attn, g_attn_out);
    cudaGetSymbolAddress((void**)&Ah, g_Ah);
    cudaGetSymbolAddress((void**)&Al, g_Al);
    cudaGetSymbolAddress((void**)&Wqh, g_Wqkv_h);
    cudaGetSymbolAddress((void**)&Wql, g_Wqkv_l);
    cudaGetSymbolAddress((void**)&Woh, g_Wout_h);
    cudaGetSymbolAddress((void**)&Wol, g_Wout_l);
    cudaGetSymbolAddress((void**)&Qh, g_Qh);
    cudaGetSymbolAddress((void**)&Ql, g_Ql);
    cudaGetSymbolAddress((void**)&Kh, g_Kh);
    cudaGetSymbolAddress((void**)&Kl, g_Kl);
    cudaGetSymbolAddress((void**)&Vh, g_Vh);
    cudaGetSymbolAddress((void**)&Vl, g_Vl);

    cudaFuncSetAttribute(gemm_tc, cudaFuncAttributeMaxDynamicSharedMemorySize,
                         GEMM_SMEM);
    cudaFuncSetAttribute(attn_tc, cudaFuncAttributeMaxDynamicSharedMemorySize,
                         ATTN_SMEM);

    // Prepass: weight transpose+split, activation split
    transpose_split<<<dim3(DIM / 32, N3 / 32), 256>>>(w_qkv, Wqh, Wql, DIM, N3);
    transpose_split<<<dim3(DIM / 32, DIM / 32), 256>>>(w_out, Woh, Wol, DIM, DIM);
    split_rows<<<(S_LEN * DIM) / 1024, 256>>>(hidden, Ah, Al);

    // 1) QKV = X @ Wqkv + b (tensor cores)
    gemm_tc<<<dim3(S_LEN / 128, N3 / 128), 256, GEMM_SMEM>>>(
        Ah, Al, Wqh, Wql, b_qkv, qkv, N3);

    // 2) RMSNorm + RoPE + split q,k,v to bf16 hi/lo
    rmsnorm_rope_split<<<S_LEN, 256>>>(qkv, cos_t, sin_t, w_qn, w_kn,
                                       Qh, Ql, Kh, Kl, Vh, Vl);

    // 3) Tensor-core flash attention
    attn_tc<<<dim3(S_LEN / 128, NH), 256, ATTN_SMEM>>>(Qh, Ql, Kh, Kl, Vh, Vl, attn);

    // 4) out = attn_out @ Wout + b (tensor cores)
    split_rows<<<(S_LEN * DIM) / 1024, 256>>>(attn, Ah, Al);
    gemm_tc<<<dim3(S_LEN / 128, DIM / 128), 256, GEMM_SMEM>>>(
        Ah, Al, Woh, Wol, b_out, out, DIM);
}

// round 5
// speedup vs baseline: 6.4342x; 1.0188x over previous
#include <cuda_runtime.h>
#include <cuda_bf16.h>
#include <cstdint>

// Shapes (fixed by the problem)
#define S_LEN 2048
#define DIM   5120
#define NH    40
#define DH    128
#define N3    15360   // 3*DIM

// ---------------------------------------------------------------------------
// Scratch (device globals: no allocation allowed in kernel_launch)
// ---------------------------------------------------------------------------
__device__ float g_qkv[(size_t)S_LEN * N3];        // 2048 x 15360 (QKV GEMM out)
__device__ __nv_bfloat16 g_Ah[(size_t)S_LEN * DIM];     // activations hi  [M][K]
__device__ __nv_bfloat16 g_Al[(size_t)S_LEN * DIM];     // activations lo
__device__ __nv_bfloat16 g_Wqkv_h[(size_t)N3 * DIM];    // w_qkv^T hi [N][K]
__device__ __nv_bfloat16 g_Wqkv_l[(size_t)N3 * DIM];
__device__ __nv_bfloat16 g_Wout_h[(size_t)DIM * DIM];   // w_out^T hi [N][K]
__device__ __nv_bfloat16 g_Wout_l[(size_t)DIM * DIM];
// bf16 hi/lo q/k (post norm+rope) and v for tensor-core attention, [s][DIM]
__device__ __nv_bfloat16 g_Qh[(size_t)S_LEN * DIM];
__device__ __nv_bfloat16 g_Ql[(size_t)S_LEN * DIM];
__device__ __nv_bfloat16 g_Kh[(size_t)S_LEN * DIM];
__device__ __nv_bfloat16 g_Kl[(size_t)S_LEN * DIM];
__device__ __nv_bfloat16 g_Vh[(size_t)S_LEN * DIM];
__device__ __nv_bfloat16 g_Vl[(size_t)S_LEN * DIM];

// ---------------------------------------------------------------------------
// Baseline-PTX helpers (sm_103 family target: no 'a' features)
// ---------------------------------------------------------------------------
__device__ __forceinline__ uint32_t smem_u32(const void* p) {
    uint32_t a;
    asm("{ .reg .u64 t; cvta.to.shared.u64 t, %1; cvt.u32.u64 %0, t; }"
        : "=r"(a) : "l"(p));
    return a;
}

#define CP_ASYNC16(dst, src) \
    asm volatile("cp.async.cg.shared.global [%0], [%1], 16;" \
        :: "r"(dst), "l"(src) : "memory")
#define CP_COMMIT() asm volatile("cp.async.commit_group;" ::: "memory")
#define CP_WAIT0()  asm volatile("cp.async.wait_group 0;" ::: "memory")
#define CP_WAIT1()  asm volatile("cp.async.wait_group 1;" ::: "memory")

#define LDMATRIX_X4(r0, r1, r2, r3, addr) \
    asm volatile("ldmatrix.sync.aligned.m8n8.x4.shared.b16 {%0,%1,%2,%3}, [%4];" \
        : "=r"(r0), "=r"(r1), "=r"(r2), "=r"(r3) : "r"(addr))
#define LDMATRIX_X4_T(r0, r1, r2, r3, addr) \
    asm volatile("ldmatrix.sync.aligned.m8n8.x4.trans.shared.b16 {%0,%1,%2,%3}, [%4];" \
        : "=r"(r0), "=r"(r1), "=r"(r2), "=r"(r3) : "r"(addr))

#define MMA_BF16(d, a, b) \
    asm volatile( \
        "mma.sync.aligned.m16n8k16.row.col.f32.bf16.bf16.f32 " \
        "{%0,%1,%2,%3}, {%4,%5,%6,%7}, {%8,%9}, {%0,%1,%2,%3};" \
        : "+f"((d)[0]), "+f"((d)[1]), "+f"((d)[2]), "+f"((d)[3]) \
        : "r"((a)[0]), "r"((a)[1]), "r"((a)[2]), "r"((a)[3]), \
          "r"((b)[0]), "r"((b)[1]))

__device__ __forceinline__ float fast_exp2(float x) {
    float y;
    asm("ex2.approx.f32 %0, %1;" : "=f"(y) : "f"(x));
    return y;
}

// fp32 pair -> packed bf16x2 hi + residual lo
__device__ __forceinline__ void split2(float a, float b, uint32_t& hi, uint32_t& lo) {
    __nv_bfloat16 ha = __float2bfloat16(a), hb = __float2bfloat16(b);
    __nv_bfloat162 h2(ha, hb);
    __nv_bfloat162 l2(__float2bfloat16(a - __bfloat162float(ha)),
                      __float2bfloat16(b - __bfloat162float(hb)));
    hi = *reinterpret_cast<uint32_t*>(&h2);
    lo = *reinterpret_cast<uint32_t*>(&l2);
}

// ---------------------------------------------------------------------------
// Prepass 1: elementwise fp32 -> (bf16 hi, bf16 lo), same layout.
// ---------------------------------------------------------------------------
__global__ __launch_bounds__(256)
void split_rows(const float* __restrict__ X, __nv_bfloat16* __restrict__ H,
                __nv_bfloat16* __restrict__ L)
{
    size_t i = ((size_t)blockIdx.x * 256 + threadIdx.x) * 4;
    float4 v = *reinterpret_cast<const float4*>(X + i);
    uint32_t h0, l0, h1, l1;
    split2(v.x, v.y, h0, l0);
    split2(v.z, v.w, h1, l1);
    uint32_t* Hp = reinterpret_cast<uint32_t*>(H + i);
    uint32_t* Lp = reinterpret_cast<uint32_t*>(L + i);
    Hp[0] = h0; Hp[1] = h1;
    Lp[0] = l0; Lp[1] = l1;
}

// ---------------------------------------------------------------------------
// Prepass 2: W[K][N] fp32 -> T_hi/T_lo [N][K] bf16 (transpose + split)
// ---------------------------------------------------------------------------
__global__ __launch_bounds__(256)
void transpose_split(const float* __restrict__ W, __nv_bfloat16* __restrict__ Th,
                     __nv_bfloat16* __restrict__ Tl, int K, int N)
{
    __shared__ float t[32][33];
    const int k0 = blockIdx.x * 32, n0 = blockIdx.y * 32;
    const int tx = threadIdx.x & 31, ty = threadIdx.x >> 5;
#pragma unroll
    for (int i = 0; i < 4; i++)
        t[ty + i * 8][tx] = W[(size_t)(k0 + ty + i * 8) * N + n0 + tx];
    __syncthreads();
#pragma unroll
    for (int i = 0; i < 4; i++) {
        const int n = n0 + ty + i * 8;
        const float v = t[tx][ty + i * 8];
        __nv_bfloat16 h = __float2bfloat16(v);
        __nv_bfloat16 l = __float2bfloat16(v - __bfloat162float(h));
        Th[(size_t)n * K + k0 + tx] = h;
        Tl[(size_t)n * K + k0 + tx] = l;
    }
}

// ---------------------------------------------------------------------------
// Tensor-core GEMM via mma.sync bf16 (hi/lo 3-term split, fp32 accum).
// One __syncthreads per chunk: the top barrier both publishes the arrived
// cp.async data AND proves all warps finished the previous chunk's MMAs on
// the buffer the new load targets.
// ---------------------------------------------------------------------------
#define BK        32
#define SPITCH    40
#define TILE_B    (128 * SPITCH * 2)
#define STAGE_B   (4 * TILE_B)
#define GEMM_SMEM (2 * STAGE_B)

__global__ __launch_bounds__(256)
void gemm_tc(const __nv_bfloat16* __restrict__ Ah, const __nv_bfloat16* __restrict__ Al,
             const __nv_bfloat16* __restrict__ Bh, const __nv_bfloat16* __restrict__ Bl,
             const float* __restrict__ bias, float* __restrict__ C, int N)
{
    constexpr int K = DIM;
    constexpr int NCHUNK = K / BK;

    extern __shared__ char dsm[];
    const uint32_t sbase = smem_u32(dsm);

    const int tid = threadIdx.x;
    const int wid = tid >> 5, lane = tid & 31;
    const int warp_m = wid & 3;
    const int warp_n = wid >> 2;
    const int row0 = blockIdx.x * 128;
    const int col0 = blockIdx.y * 128;

    const __nv_bfloat16* gA[4] = { Ah + (size_t)row0 * K, Al + (size_t)row0 * K,
                                   Bh + (size_t)col0 * K, Bl + (size_t)col0 * K };

    auto load_stage = [&](int stage, int koff) {
        const uint32_t sb = sbase + stage * STAGE_B;
#pragma unroll
        for (int t = 0; t < 4; ++t) {
#pragma unroll
            for (int g2 = 0; g2 < 2; ++g2) {
                const int g = tid + g2 * 256;
                const int row = g >> 2, c16 = g & 3;
                const __nv_bfloat16* src = gA[t] + (size_t)row * K + koff + c16 * 8;
                const uint32_t dst = sb + t * TILE_B + row * (SPITCH * 2) + c16 * 16;
                CP_ASYNC16(dst, src);
            }
        }
    };

    float acc[2][8][4];
#pragma unroll
    for (int i = 0; i < 2; i++)
#pragma unroll
        for (int j = 0; j < 8; j++)
#pragma unroll
            for (int v = 0; v < 4; v++) acc[i][j][v] = 0.f;

    load_stage(0, 0);
    CP_COMMIT();

    for (int c = 0; c < NCHUNK; ++c) {
        CP_WAIT0();
        __syncthreads();
        if (c + 1 < NCHUNK) {
            load_stage((c + 1) & 1, (c + 1) * BK);
            CP_COMMIT();
        }

        const uint32_t sb = sbase + (c & 1) * STAGE_B;
        const uint32_t sAh = sb, sAl = sb + TILE_B;
        const uint32_t sBh = sb + 2 * TILE_B, sBl = sb + 3 * TILE_B;

#pragma unroll
        for (int k16 = 0; k16 < 2; ++k16) {
            const uint32_t kb = k16 * 32;

            uint32_t a_h[2][4], a_l[2][4];
#pragma unroll
            for (int mf = 0; mf < 2; ++mf) {
                const uint32_t ro = (warp_m * 32 + mf * 16 + (lane & 15)) * (SPITCH * 2)
                                    + ((lane >> 4) * 16) + kb;
                LDMATRIX_X4(a_h[mf][0], a_h[mf][1], a_h[mf][2], a_h[mf][3], sAh + ro);
                LDMATRIX_X4(a_l[mf][0], a_l[mf][1], a_l[mf][2], a_l[mf][3], sAl + ro);
            }
            uint32_t b_h[4][4], b_l[4][4];
#pragma unroll
            for (int nf = 0; nf < 4; ++nf) {
                const uint32_t ro = (warp_n * 64 + nf * 16 + (lane & 7) + ((lane >> 4) << 3))
                                    * (SPITCH * 2) + (((lane >> 3) & 1) * 16) + kb;
                LDMATRIX_X4(b_h[nf][0], b_h[nf][1], b_h[nf][2], b_h[nf][3], sBh + ro);
                LDMATRIX_X4(b_l[nf][0], b_l[nf][1], b_l[nf][2], b_l[nf][3], sBl + ro);
            }
#pragma unroll
            for (int mf = 0; mf < 2; ++mf)
#pragma unroll
                for (int nf = 0; nf < 4; ++nf)
#pragma unroll
                    for (int half = 0; half < 2; ++half) {
                        uint32_t bh2[2] = { b_h[nf][half * 2], b_h[nf][half * 2 + 1] };
                        uint32_t bl2[2] = { b_l[nf][half * 2], b_l[nf][half * 2 + 1] };
                        float* d = acc[mf][nf * 2 + half];
                        MMA_BF16(d, a_h[mf], bh2);
                        MMA_BF16(d, a_h[mf], bl2);
                        MMA_BF16(d, a_l[mf], bh2);
                    }
        }
    }

#pragma unroll
    for (int mf = 0; mf < 2; ++mf) {
        const int r0 = row0 + warp_m * 32 + mf * 16 + (lane >> 2);
#pragma unroll
        for (int nf = 0; nf < 8; ++nf) {
            const int col = col0 + warp_n * 64 + nf * 8 + (lane & 3) * 2;
            const float b0 = bias[col], b1 = bias[col + 1];
            float* p0 = C + (size_t)r0 * N + col;
            float* p1 = C + (size_t)(r0 + 8) * N + col;
            *reinterpret_cast<float2*>(p0) =
                make_float2(acc[mf][nf][0] + b0, acc[mf][nf][1] + b1);
            *reinterpret_cast<float2*>(p1) =
                make_float2(acc[mf][nf][2] + b0, acc[mf][nf][3] + b1);
        }
    }
}

// ---------------------------------------------------------------------------
// Fused RMSNorm(q,k) + RoPE + hi/lo split of q,k,v -> bf16 buffers [s][DIM].
// ---------------------------------------------------------------------------
__global__ __launch_bounds__(256)
void rmsnorm_rope_split(const float* __restrict__ qkv,
                        const float* __restrict__ cos_t,
                        const float* __restrict__ sin_t,
                        const float* __restrict__ wq,
                        const float* __restrict__ wk,
                        __nv_bfloat16* __restrict__ Qh, __nv_bfloat16* __restrict__ Ql,
                        __nv_bfloat16* __restrict__ Kh, __nv_bfloat16* __restrict__ Kl,
                        __nv_bfloat16* __restrict__ Vh, __nv_bfloat16* __restrict__ Vl)
{
    const int s = blockIdx.x;
    const float* q = qkv + (size_t)s * N3;
    const float* k = q + DIM;
    const float* v = k + DIM;

    float sq = 0.f, sk = 0.f;
    for (int i = threadIdx.x; i < DIM; i += blockDim.x) {
        float a = q[i]; sq += a * a;
        float b = k[i]; sk += b * b;
    }
#pragma unroll
    for (int o = 16; o; o >>= 1) {
        sq += __shfl_xor_sync(0xffffffffu, sq, o);
        sk += __shfl_xor_sync(0xffffffffu, sk, o);
    }
    __shared__ float red[2][32];
    const int wid = threadIdx.x >> 5, lid = threadIdx.x & 31;
    if (lid == 0) { red[0][wid] = sq; red[1][wid] = sk; }
    __syncthreads();
    if (threadIdx.x == 0) {
        float a = 0.f, b = 0.f;
        for (int i = 0; i < 8; i++) { a += red[0][i]; b += red[1][i]; }
        red[0][0] = a; red[1][0] = b;
    }
    __syncthreads();
    const float rq = rsqrtf(red[0][0] / (float)DIM + 1e-6f);
    const float rk = rsqrtf(red[1][0] / (float)DIM + 1e-6f);

    const size_t ob = (size_t)s * DIM;
    for (int p = threadIdx.x; p < DIM / 2; p += blockDim.x) {
        const int e = 2 * p, o = 2 * p + 1;
        const int ih = p & 63;
        const float ce = cos_t[s * DH + 2 * ih];
        const float so = sin_t[s * DH + 2 * ih + 1];

        float qe = q[e] * rq * wq[e], qo = q[o] * rq * wq[o];
        float ke = k[e] * rk * wk[e], ko = k[o] * rk * wk[o];
        uint32_t hi, lo;
        split2(qe * ce - qo * so, qe * so + qo * ce, hi, lo);
        *reinterpret_cast<uint32_t*>(Qh + ob + e) = hi;
        *reinterpret_cast<uint32_t*>(Ql + ob + e) = lo;
        split2(ke * ce - ko * so, ke * so + ko * ce, hi, lo);
        *reinterpret_cast<uint32_t*>(Kh + ob + e) = hi;
        *reinterpret_cast<uint32_t*>(Kl + ob + e) = lo;
        split2(v[e], v[o], hi, lo);
        *reinterpret_cast<uint32_t*>(Vh + ob + e) = hi;
        *reinterpret_cast<uint32_t*>(Vl + ob + e) = lo;
    }
}

// ---------------------------------------------------------------------------
// Tensor-core flash attention (mma.sync bf16 hi/lo, exp2-domain softmax).
// Output written directly as bf16 hi/lo (operands for the out-proj GEMM).
// ---------------------------------------------------------------------------
#define A_BK     64
#define A_PITCHB 272
#define A_QBYTES (128 * A_PITCHB)
#define A_KTILE  (A_BK * A_PITCHB)
#define A_STAGE  (4 * A_KTILE)
#define ATTN_SMEM (2 * A_QBYTES + 2 * A_STAGE)

__global__ __launch_bounds__(256)
void attn_tc(const __nv_bfloat16* __restrict__ Qh, const __nv_bfloat16* __restrict__ Ql,
             const __nv_bfloat16* __restrict__ Kh, const __nv_bfloat16* __restrict__ Kl,
             const __nv_bfloat16* __restrict__ Vh, const __nv_bfloat16* __restrict__ Vl,
             __nv_bfloat16* __restrict__ Oh, __nv_bfloat16* __restrict__ Ol)
{
    extern __shared__ char dsm[];
    const uint32_t base = smem_u32(dsm);
    const uint32_t sQh = base, sQl = base + A_QBYTES;
    const uint32_t stage0 = base + 2 * A_QBYTES;

    const int qb = blockIdx.x;
    const int h  = blockIdx.y;
    const int tid = threadIdx.x;
    const int warp = tid >> 5, lane = tid & 31;

    const __nv_bfloat16* kvsrc[4] = { Kh, Kl, Vh, Vl };

    {
        const size_t qoff = (size_t)(qb * 128) * DIM + h * DH;
#pragma unroll
        for (int g = 0; g < 8; ++g) {
            const int idx = tid + g * 256;
            const int row = idx >> 4, c = idx & 15;
            const size_t so = qoff + (size_t)row * DIM + c * 8;
            CP_ASYNC16(sQh + row * A_PITCHB + c * 16, Qh + so);
            CP_ASYNC16(sQl + row * A_PITCHB + c * 16, Ql + so);
        }
    }
    auto load_kv = [&](uint32_t st, int kt) {
        const size_t koff = (size_t)(kt * A_BK) * DIM + h * DH;
#pragma unroll
        for (int g = 0; g < 16; ++g) {
            const int t = g >> 2;
            const int idx = tid + (g & 3) * 256;
            const int row = idx >> 4, c = idx & 15;
            CP_ASYNC16(st + t * A_KTILE + row * A_PITCHB + c * 16,
                       kvsrc[t] + koff + (size_t)row * DIM + c * 8);
        }
    };

    load_kv(stage0, 0);
    CP_COMMIT();
    load_kv(stage0 + A_STAGE, 1);
    CP_COMMIT();

    float O[16][4];
#pragma unroll
    for (int i = 0; i < 16; i++)
#pragma unroll
        for (int j = 0; j < 4; j++) O[i][j] = 0.f;
    float m_run[2] = { -1e30f, -1e30f };
    float l_run[2] = { 0.f, 0.f };
    // scale in log2 domain: 128^-0.5 * log2(e)
    const float scale2 = 0.08838834764831845f * 1.4426950408889634f;

    constexpr int NT = S_LEN / A_BK;

    for (int kt = 0; kt < NT; ++kt) {
        if (kt == NT - 1) { CP_WAIT0(); } else { CP_WAIT1(); }
        __syncthreads();

        const uint32_t st = stage0 + (kt & 1) * A_STAGE;
        const uint32_t sKh = st, sKl = st + A_KTILE;
        const uint32_t sVh = st + 2 * A_KTILE, sVl = st + 3 * A_KTILE;

        // ---- S = Q K^T (16 x 64 per warp), 3-term split ----
        float sacc[8][4];
#pragma unroll
        for (int i = 0; i < 8; i++)
#pragma unroll
            for (int j = 0; j < 4; j++) sacc[i][j] = 0.f;

#pragma unroll
        for (int ks = 0; ks < 8; ++ks) {
            const uint32_t kb = ks * 32;
            uint32_t aH[4], aL[4];
            const uint32_t aro = (warp * 16 + (lane & 15)) * A_PITCHB
                                 + ((lane >> 4) * 16) + kb;
            LDMATRIX_X4(aH[0], aH[1], aH[2], aH[3], sQh + aro);
            LDMATRIX_X4(aL[0], aL[1], aL[2], aL[3], sQl + aro);
#pragma unroll
            for (int nb = 0; nb < 4; ++nb) {
                uint32_t bH[4], bL[4];
                const uint32_t bro = (nb * 16 + (lane & 7) + ((lane >> 4) << 3))
                                     * A_PITCHB + (((lane >> 3) & 1) * 16) + kb;
                LDMATRIX_X4(bH[0], bH[1], bH[2], bH[3], sKh + bro);
                LDMATRIX_X4(bL[0], bL[1], bL[2], bL[3], sKl + bro);
#pragma unroll
                for (int half = 0; half < 2; ++half) {
                    uint32_t bh2[2] = { bH[half * 2], bH[half * 2 + 1] };
                    uint32_t bl2[2] = { bL[half * 2], bL[half * 2 + 1] };
                    float* d = sacc[nb * 2 + half];
                    MMA_BF16(d, aH, bh2);
                    MMA_BF16(d, aH, bl2);
                    MMA_BF16(d, aL, bh2);
                }
            }
        }

        // ---- online softmax in log2 domain ----
        float mt0 = -1e30f, mt1 = -1e30f;
#pragma unroll
        for (int f = 0; f < 8; ++f) {
            sacc[f][0] *= scale2; sacc[f][1] *= scale2;
            sacc[f][2] *= scale2; sacc[f][3] *= scale2;
            mt0 = fmaxf(mt0, fmaxf(sacc[f][0], sacc[f][1]));
            mt1 = fmaxf(mt1, fmaxf(sacc[f][2], sacc[f][3]));
        }
        mt0 = fmaxf(mt0, __shfl_xor_sync(0xffffffffu, mt0, 1));
        mt0 = fmaxf(mt0, __shfl_xor_sync(0xffffffffu, mt0, 2));
        mt1 = fmaxf(mt1, __shfl_xor_sync(0xffffffffu, mt1, 1));
        mt1 = fmaxf(mt1, __shfl_xor_sync(0xffffffffu, mt1, 2));
        const float mn0 = fmaxf(m_run[0], mt0), mn1 = fmaxf(m_run[1], mt1);
        const float al0 = fast_exp2(m_run[0] - mn0), al1 = fast_exp2(m_run[1] - mn1);
        m_run[0] = mn0; m_run[1] = mn1;

        float ls0 = 0.f, ls1 = 0.f;
#pragma unroll
        for (int f = 0; f < 8; ++f) {
            sacc[f][0] = fast_exp2(sacc[f][0] - mn0);
            sacc[f][1] = fast_exp2(sacc[f][1] - mn0);
            sacc[f][2] = fast_exp2(sacc[f][2] - mn1);
            sacc[f][3] = fast_exp2(sacc[f][3] - mn1);
            ls0 += sacc[f][0] + sacc[f][1];
            ls1 += sacc[f][2] + sacc[f][3];
        }
        ls0 += __shfl_xor_sync(0xffffffffu, ls0, 1);
        ls0 += __shfl_xor_sync(0xffffffffu, ls0, 2);
        ls1 += __shfl_xor_sync(0xffffffffu, ls1, 1);
        ls1 += __shfl_xor_sync(0xffffffffu, ls1, 2);
        l_run[0] = l_run[0] * al0 + ls0;
        l_run[1] = l_run[1] * al1 + ls1;

#pragma unroll
        for (int i = 0; i < 16; i++) {
            O[i][0] *= al0; O[i][1] *= al0;
            O[i][2] *= al1; O[i][3] *= al1;
        }

        // P accum-frags -> A-operand frags (hi/lo)
        uint32_t pH[4][4], pL[4][4];
#pragma unroll
        for (int j = 0; j < 4; ++j) {
            split2(sacc[2 * j][0],     sacc[2 * j][1],     pH[j][0], pL[j][0]);
            split2(sacc[2 * j][2],     sacc[2 * j][3],     pH[j][1], pL[j][1]);
            split2(sacc[2 * j + 1][0], sacc[2 * j + 1][1], pH[j][2], pL[j][2]);
            split2(sacc[2 * j + 1][2], sacc[2 * j + 1][3], pH[j][3], pL[j][3]);
        }

        // ---- O += P V (V via ldmatrix.trans), 3-term split ----
#pragma unroll
        for (int ks = 0; ks < 4; ++ks) {
            const uint32_t krow = ks * 16 + (lane & 7) + (((lane >> 3) & 1) * 8);
#pragma unroll
            for (int nb = 0; nb < 8; ++nb) {
                const uint32_t ro = krow * A_PITCHB + nb * 32 + ((lane >> 4) * 16);
                uint32_t bH[4], bL[4];
                LDMATRIX_X4_T(bH[0], bH[1], bH[2], bH[3], sVh + ro);
                LDMATRIX_X4_T(bL[0], bL[1], bL[2], bL[3], sVl + ro);
#pragma unroll
                for (int half = 0; half < 2; ++half) {
                    uint32_t bh2[2] = { bH[half * 2], bH[half * 2 + 1] };
                    uint32_t bl2[2] = { bL[half * 2], bL[half * 2 + 1] };
                    float* d = O[nb * 2 + half];
                    MMA_BF16(d, pH[ks], bh2);
                    MMA_BF16(d, pH[ks], bl2);
                    MMA_BF16(d, pL[ks], bh2);
                }
            }
        }

        __syncthreads();
        if (kt + 2 < NT) {
            load_kv(stage0 + (kt & 1) * A_STAGE, kt + 2);
            CP_COMMIT();
        }
    }

    // ---- epilogue: write bf16 hi/lo operands for out-proj GEMM ----
    const float inv0 = 1.f / l_run[0], inv1 = 1.f / l_run[1];
    const int s0 = qb * 128 + warp * 16 + (lane >> 2);
#pragma unroll
    for (int nf = 0; nf < 16; ++nf) {
        const int col = h * DH + nf * 8 + (lane & 3) * 2;
        uint32_t hi, lo;
        split2(O[nf][0] * inv0, O[nf][1] * inv0, hi, lo);
        *reinterpret_cast<uint32_t*>(Oh + (size_t)s0 * DIM + col) = hi;
        *reinterpret_cast<uint32_t*>(Ol + (size_t)s0 * DIM + col) = lo;
        split2(O[nf][2] * inv1, O[nf][3] * inv1, hi, lo);
        *reinterpret_cast<uint32_t*>(Oh + (size_t)(s0 + 8) * DIM + col) = hi;
        *reinterpret_cast<uint32_t*>(Ol + (size_t)(s0 + 8) * DIM + col) = lo;
    }
}

// ---------------------------------------------------------------------------
// Launch
// ---------------------------------------------------------------------------
extern "C" void kernel_launch(void* const* d_in, const int* in_sizes, int n_in,
                              void* d_out, int out_size)
{
    const float* hidden = (const float*)d_in[0];
    const float* cos_t  = (const float*)d_in[1];
    const float* sin_t  = (const float*)d_in[2];
    const float* w_qkv  = (const float*)d_in[3];
    const float* b_qkv  = (const float*)d_in[4];
    const float* w_qn   = (const float*)d_in[5];
    const float* w_kn   = (const float*)d_in[6];
    const float* w_out  = (const float*)d_in[7];
    const float* b_out  = (const float*)d_in[8];
    float* out = (float*)d_out;

    float* qkv;
    __nv_bfloat16 *Ah, *Al, *Wqh, *Wql, *Woh, *Wol, *Qh, *Ql, *Kh, *Kl, *Vh, *Vl;
    cudaGetSymbolAddress((void**)&qkv, g_qkv);
    cudaGetSymbolAddress((void**)&Ah, g_Ah);
    cudaGetSymbolAddress((void**)&Al, g_Al);
    cudaGetSymbolAddress((void**)&Wqh, g_Wqkv_h);
    cudaGetSymbolAddress((void**)&Wql, g_Wqkv_l);
    cudaGetSymbolAddress((void**)&Woh, g_Wout_h);
    cudaGetSymbolAddress((void**)&Wol, g_Wout_l);
    cudaGetSymbolAddress((void**)&Qh, g_Qh);
    cudaGetSymbolAddress((void**)&Ql, g_Ql);
    cudaGetSymbolAddress((void**)&Kh, g_Kh);
    cudaGetSymbolAddress((void**)&Kl, g_Kl);
    cudaGetSymbolAddress((void**)&Vh, g_Vh);
    cudaGetSymbolAddress((void**)&Vl, g_Vl);

    cudaFuncSetAttribute(gemm_tc, cudaFuncAttributeMaxDynamicSharedMemorySize,
                         GEMM_SMEM);
    cudaFuncSetAttribute(attn_tc, cudaFuncAttributeMaxDynamicSharedMemorySize,
                         ATTN_SMEM);

    // Prepass: weight transpose+split, activation split
    transpose_split<<<dim3(DIM / 32, N3 / 32), 256>>>(w_qkv, Wqh, Wql, DIM, N3);
    transpose_split<<<dim3(DIM / 32, DIM / 32), 256>>>(w_out, Woh, Wol, DIM, DIM);
    split_rows<<<(S_LEN * DIM) / 1024, 256>>>(hidden, Ah, Al);

    // 1) QKV = X @ Wqkv + b (tensor cores)
    gemm_tc<<<dim3(S_LEN / 128, N3 / 128), 256, GEMM_SMEM>>>(
        Ah, Al, Wqh, Wql, b_qkv, qkv, N3);

    // 2) RMSNorm + RoPE + split q,k,v to bf16 hi/lo
    rmsnorm_rope_split<<<S_LEN, 256>>>(qkv, cos_t, sin_t, w_qn, w_kn,
                                       Qh, Ql, Kh, Kl, Vh, Vl);

    // 3) Tensor-core flash attention (emits bf16 hi/lo directly into Ah/Al)
    attn_tc<<<dim3(S_LEN / 128, NH), 256, ATTN_SMEM>>>(Qh, Ql, Kh, Kl, Vh, Vl, Ah, Al);

    // 4) out = attn_out @ Wout + b (tensor cores)
    gemm_tc<<<dim3(S_LEN / 128, DIM / 128), 256, GEMM_SMEM>>>(
        Ah, Al, Woh, Wol, b_out, out, DIM);
}

// round 6
// speedup vs baseline: 6.4833x; 1.0076x over previous
#include <cuda_runtime.h>
#include <cuda_bf16.h>
#include <cstdint>

// Shapes (fixed by the problem)
#define S_LEN 2048
#define DIM   5120
#define NH    40
#define DH    128
#define N3    15360   // 3*DIM

// ---------------------------------------------------------------------------
// Scratch (device globals: no allocation allowed in kernel_launch)
// ---------------------------------------------------------------------------
__device__ float g_qkv[(size_t)S_LEN * N3];        // 2048 x 15360 (QKV GEMM out)
__device__ __nv_bfloat16 g_Ah[(size_t)S_LEN * DIM];     // activations hi  [M][K]
__device__ __nv_bfloat16 g_Al[(size_t)S_LEN * DIM];     // activations lo
__device__ __nv_bfloat16 g_Wqkv_h[(size_t)N3 * DIM];    // w_qkv^T hi [N][K]
__device__ __nv_bfloat16 g_Wqkv_l[(size_t)N3 * DIM];
__device__ __nv_bfloat16 g_Wout_h[(size_t)DIM * DIM];   // w_out^T hi [N][K]
__device__ __nv_bfloat16 g_Wout_l[(size_t)DIM * DIM];
// bf16 hi/lo q/k (post norm+rope) and v for tensor-core attention, [s][DIM]
__device__ __nv_bfloat16 g_Qh[(size_t)S_LEN * DIM];
__device__ __nv_bfloat16 g_Ql[(size_t)S_LEN * DIM];
__device__ __nv_bfloat16 g_Kh[(size_t)S_LEN * DIM];
__device__ __nv_bfloat16 g_Kl[(size_t)S_LEN * DIM];
__device__ __nv_bfloat16 g_Vh[(size_t)S_LEN * DIM];
__device__ __nv_bfloat16 g_Vl[(size_t)S_LEN * DIM];

// ---------------------------------------------------------------------------
// Baseline-PTX helpers (sm_103 family target: no 'a' features)
// ---------------------------------------------------------------------------
__device__ __forceinline__ uint32_t smem_u32(const void* p) {
    uint32_t a;
    asm("{ .reg .u64 t; cvta.to.shared.u64 t, %1; cvt.u32.u64 %0, t; }"
        : "=r"(a) : "l"(p));
    return a;
}

#define CP_ASYNC16(dst, src) \
    asm volatile("cp.async.cg.shared.global [%0], [%1], 16;" \
        :: "r"(dst), "l"(src) : "memory")
#define CP_COMMIT() asm volatile("cp.async.commit_group;" ::: "memory")
#define CP_WAIT0()  asm volatile("cp.async.wait_group 0;" ::: "memory")
#define CP_WAIT1()  asm volatile("cp.async.wait_group 1;" ::: "memory")

#define LDMATRIX_X4(r0, r1, r2, r3, addr) \
    asm volatile("ldmatrix.sync.aligned.m8n8.x4.shared.b16 {%0,%1,%2,%3}, [%4];" \
        : "=r"(r0), "=r"(r1), "=r"(r2), "=r"(r3) : "r"(addr))
#define LDMATRIX_X4_T(r0, r1, r2, r3, addr) \
    asm volatile("ldmatrix.sync.aligned.m8n8.x4.trans.shared.b16 {%0,%1,%2,%3}, [%4];" \
        : "=r"(r0), "=r"(r1), "=r"(r2), "=r"(r3) : "r"(addr))

#define MMA_BF16(d, a, b) \
    asm volatile( \
        "mma.sync.aligned.m16n8k16.row.col.f32.bf16.bf16.f32 " \
        "{%0,%1,%2,%3}, {%4,%5,%6,%7}, {%8,%9}, {%0,%1,%2,%3};" \
        : "+f"((d)[0]), "+f"((d)[1]), "+f"((d)[2]), "+f"((d)[3]) \
        : "r"((a)[0]), "r"((a)[1]), "r"((a)[2]), "r"((a)[3]), \
          "r"((b)[0]), "r"((b)[1]))

__device__ __forceinline__ float fast_exp2(float x) {
    float y;
    asm("ex2.approx.f32 %0, %1;" : "=f"(y) : "f"(x));
    return y;
}

// fp32 pair -> packed bf16x2 hi + residual lo
__device__ __forceinline__ void split2(float a, float b, uint32_t& hi, uint32_t& lo) {
    __nv_bfloat16 ha = __float2bfloat16(a), hb = __float2bfloat16(b);
    __nv_bfloat162 h2(ha, hb);
    __nv_bfloat162 l2(__float2bfloat16(a - __bfloat162float(ha)),
                      __float2bfloat16(b - __bfloat162float(hb)));
    hi = *reinterpret_cast<uint32_t*>(&h2);
    lo = *reinterpret_cast<uint32_t*>(&l2);
}

// ---------------------------------------------------------------------------
// Prepass 1: elementwise fp32 -> (bf16 hi, bf16 lo), same layout.
// ---------------------------------------------------------------------------
__global__ __launch_bounds__(256)
void split_rows(const float* __restrict__ X, __nv_bfloat16* __restrict__ H,
                __nv_bfloat16* __restrict__ L)
{
    size_t i = ((size_t)blockIdx.x * 256 + threadIdx.x) * 4;
    float4 v = *reinterpret_cast<const float4*>(X + i);
    uint32_t h0, l0, h1, l1;
    split2(v.x, v.y, h0, l0);
    split2(v.z, v.w, h1, l1);
    uint32_t* Hp = reinterpret_cast<uint32_t*>(H + i);
    uint32_t* Lp = reinterpret_cast<uint32_t*>(L + i);
    Hp[0] = h0; Hp[1] = h1;
    Lp[0] = l0; Lp[1] = l1;
}

// ---------------------------------------------------------------------------
// Prepass 2: W[K][N] fp32 -> T_hi/T_lo [N][K] bf16 (transpose + split)
// ---------------------------------------------------------------------------
__global__ __launch_bounds__(256)
void transpose_split(const float* __restrict__ W, __nv_bfloat16* __restrict__ Th,
                     __nv_bfloat16* __restrict__ Tl, int K, int N)
{
    __shared__ float t[32][33];
    const int k0 = blockIdx.x * 32, n0 = blockIdx.y * 32;
    const int tx = threadIdx.x & 31, ty = threadIdx.x >> 5;
#pragma unroll
    for (int i = 0; i < 4; i++)
        t[ty + i * 8][tx] = W[(size_t)(k0 + ty + i * 8) * N + n0 + tx];
    __syncthreads();
#pragma unroll
    for (int i = 0; i < 4; i++) {
        const int n = n0 + ty + i * 8;
        const float v = t[tx][ty + i * 8];
        __nv_bfloat16 h = __float2bfloat16(v);
        __nv_bfloat16 l = __float2bfloat16(v - __bfloat162float(h));
        Th[(size_t)n * K + k0 + tx] = h;
        Tl[(size_t)n * K + k0 + tx] = l;
    }
}

// ---------------------------------------------------------------------------
// Tensor-core GEMM via mma.sync bf16 (hi/lo 3-term split, fp32 accum).
// MMA issue is organized as three passes (hh, hl, lh) over all 16 independent
// accumulators so same-accumulator MMAs are 15 issues apart (RAW hidden).
// Per-accumulator order remains hh -> hl -> lh (bitwise-identical results).
// ---------------------------------------------------------------------------
#define BK        32
#define SPITCH    40
#define TILE_B    (128 * SPITCH * 2)
#define STAGE_B   (4 * TILE_B)
#define GEMM_SMEM (2 * STAGE_B)

__global__ __launch_bounds__(256)
void gemm_tc(const __nv_bfloat16* __restrict__ Ah, const __nv_bfloat16* __restrict__ Al,
             const __nv_bfloat16* __restrict__ Bh, const __nv_bfloat16* __restrict__ Bl,
             const float* __restrict__ bias, float* __restrict__ C, int N)
{
    constexpr int K = DIM;
    constexpr int NCHUNK = K / BK;

    extern __shared__ char dsm[];
    const uint32_t sbase = smem_u32(dsm);

    const int tid = threadIdx.x;
    const int wid = tid >> 5, lane = tid & 31;
    const int warp_m = wid & 3;
    const int warp_n = wid >> 2;
    const int row0 = blockIdx.x * 128;
    const int col0 = blockIdx.y * 128;

    const __nv_bfloat16* gA[4] = { Ah + (size_t)row0 * K, Al + (size_t)row0 * K,
                                   Bh + (size_t)col0 * K, Bl + (size_t)col0 * K };

    auto load_stage = [&](int stage, int koff) {
        const uint32_t sb = sbase + stage * STAGE_B;
#pragma unroll
        for (int t = 0; t < 4; ++t) {
#pragma unroll
            for (int g2 = 0; g2 < 2; ++g2) {
                const int g = tid + g2 * 256;
                const int row = g >> 2, c16 = g & 3;
                const __nv_bfloat16* src = gA[t] + (size_t)row * K + koff + c16 * 8;
                const uint32_t dst = sb + t * TILE_B + row * (SPITCH * 2) + c16 * 16;
                CP_ASYNC16(dst, src);
            }
        }
    };

    float acc[2][8][4];
#pragma unroll
    for (int i = 0; i < 2; i++)
#pragma unroll
        for (int j = 0; j < 8; j++)
#pragma unroll
            for (int v = 0; v < 4; v++) acc[i][j][v] = 0.f;

    load_stage(0, 0);
    CP_COMMIT();

    for (int c = 0; c < NCHUNK; ++c) {
        CP_WAIT0();
        __syncthreads();
        if (c + 1 < NCHUNK) {
            load_stage((c + 1) & 1, (c + 1) * BK);
            CP_COMMIT();
        }

        const uint32_t sb = sbase + (c & 1) * STAGE_B;
        const uint32_t sAh = sb, sAl = sb + TILE_B;
        const uint32_t sBh = sb + 2 * TILE_B, sBl = sb + 3 * TILE_B;

#pragma unroll
        for (int k16 = 0; k16 < 2; ++k16) {
            const uint32_t kb = k16 * 32;

            uint32_t a_h[2][4], a_l[2][4];
#pragma unroll
            for (int mf = 0; mf < 2; ++mf) {
                const uint32_t ro = (warp_m * 32 + mf * 16 + (lane & 15)) * (SPITCH * 2)
                                    + ((lane >> 4) * 16) + kb;
                LDMATRIX_X4(a_h[mf][0], a_h[mf][1], a_h[mf][2], a_h[mf][3], sAh + ro);
                LDMATRIX_X4(a_l[mf][0], a_l[mf][1], a_l[mf][2], a_l[mf][3], sAl + ro);
            }
            uint32_t b_h[4][4], b_l[4][4];
#pragma unroll
            for (int nf = 0; nf < 4; ++nf) {
                const uint32_t ro = (warp_n * 64 + nf * 16 + (lane & 7) + ((lane >> 4) << 3))
                                    * (SPITCH * 2) + (((lane >> 3) & 1) * 16) + kb;
                LDMATRIX_X4(b_h[nf][0], b_h[nf][1], b_h[nf][2], b_h[nf][3], sBh + ro);
                LDMATRIX_X4(b_l[nf][0], b_l[nf][1], b_l[nf][2], b_l[nf][3], sBl + ro);
            }
            // Pass 1: hh into all 16 accumulators
#pragma unroll
            for (int mf = 0; mf < 2; ++mf)
#pragma unroll
                for (int nf = 0; nf < 4; ++nf)
#pragma unroll
                    for (int half = 0; half < 2; ++half) {
                        uint32_t b2[2] = { b_h[nf][half * 2], b_h[nf][half * 2 + 1] };
                        MMA_BF16(acc[mf][nf * 2 + half], a_h[mf], b2);
                    }
            // Pass 2: hl
#pragma unroll
            for (int mf = 0; mf < 2; ++mf)
#pragma unroll
                for (int nf = 0; nf < 4; ++nf)
#pragma unroll
                    for (int half = 0; half < 2; ++half) {
                        uint32_t b2[2] = { b_l[nf][half * 2], b_l[nf][half * 2 + 1] };
                        MMA_BF16(acc[mf][nf * 2 + half], a_h[mf], b2);
                    }
            // Pass 3: lh
#pragma unroll
            for (int mf = 0; mf < 2; ++mf)
#pragma unroll
                for (int nf = 0; nf < 4; ++nf)
#pragma unroll
                    for (int half = 0; half < 2; ++half) {
                        uint32_t b2[2] = { b_h[nf][half * 2], b_h[nf][half * 2 + 1] };
                        MMA_BF16(acc[mf][nf * 2 + half], a_l[mf], b2);
                    }
        }
    }

#pragma unroll
    for (int mf = 0; mf < 2; ++mf) {
        const int r0 = row0 + warp_m * 32 + mf * 16 + (lane >> 2);
#pragma unroll
        for (int nf = 0; nf < 8; ++nf) {
            const int col = col0 + warp_n * 64 + nf * 8 + (lane & 3) * 2;
            const float b0 = bias[col], b1 = bias[col + 1];
            float* p0 = C + (size_t)r0 * N + col;
            float* p1 = C + (size_t)(r0 + 8) * N + col;
            *reinterpret_cast<float2*>(p0) =
                make_float2(acc[mf][nf][0] + b0, acc[mf][nf][1] + b1);
            *reinterpret_cast<float2*>(p1) =
                make_float2(acc[mf][nf][2] + b0, acc[mf][nf][3] + b1);
        }
    }
}

// ---------------------------------------------------------------------------
// Fused RMSNorm(q,k) + RoPE + hi/lo split of q,k,v -> bf16 buffers [s][DIM].
// ---------------------------------------------------------------------------
__global__ __launch_bounds__(256)
void rmsnorm_rope_split(const float* __restrict__ qkv,
                        const float* __restrict__ cos_t,
                        const float* __restrict__ sin_t,
                        const float* __restrict__ wq,
                        const float* __restrict__ wk,
                        __nv_bfloat16* __restrict__ Qh, __nv_bfloat16* __restrict__ Ql,
                        __nv_bfloat16* __restrict__ Kh, __nv_bfloat16* __restrict__ Kl,
                        __nv_bfloat16* __restrict__ Vh, __nv_bfloat16* __restrict__ Vl)
{
    const int s = blockIdx.x;
    const float* q = qkv + (size_t)s * N3;
    const float* k = q + DIM;
    const float* v = k + DIM;

    float sq = 0.f, sk = 0.f;
    for (int i = threadIdx.x; i < DIM; i += blockDim.x) {
        float a = q[i]; sq += a * a;
        float b = k[i]; sk += b * b;
    }
#pragma unroll
    for (int o = 16; o; o >>= 1) {
        sq += __shfl_xor_sync(0xffffffffu, sq, o);
        sk += __shfl_xor_sync(0xffffffffu, sk, o);
    }
    __shared__ float red[2][32];
    const int wid = threadIdx.x >> 5, lid = threadIdx.x & 31;
    if (lid == 0) { red[0][wid] = sq; red[1][wid] = sk; }
    __syncthreads();
    if (threadIdx.x == 0) {
        float a = 0.f, b = 0.f;
        for (int i = 0; i < 8; i++) { a += red[0][i]; b += red[1][i]; }
        red[0][0] = a; red[1][0] = b;
    }
    __syncthreads();
    const float rq = rsqrtf(red[0][0] / (float)DIM + 1e-6f);
    const float rk = rsqrtf(red[1][0] / (float)DIM + 1e-6f);

    const size_t ob = (size_t)s * DIM;
    for (int p = threadIdx.x; p < DIM / 2; p += blockDim.x) {
        const int e = 2 * p, o = 2 * p + 1;
        const int ih = p & 63;
        const float ce = cos_t[s * DH + 2 * ih];
        const float so = sin_t[s * DH + 2 * ih + 1];

        float qe = q[e] * rq * wq[e], qo = q[o] * rq * wq[o];
        float ke = k[e] * rk * wk[e], ko = k[o] * rk * wk[o];
        uint32_t hi, lo;
        split2(qe * ce - qo * so, qe * so + qo * ce, hi, lo);
        *reinterpret_cast<uint32_t*>(Qh + ob + e) = hi;
        *reinterpret_cast<uint32_t*>(Ql + ob + e) = lo;
        split2(ke * ce - ko * so, ke * so + ko * ce, hi, lo);
        *reinterpret_cast<uint32_t*>(Kh + ob + e) = hi;
        *reinterpret_cast<uint32_t*>(Kl + ob + e) = lo;
        split2(v[e], v[o], hi, lo);
        *reinterpret_cast<uint32_t*>(Vh + ob + e) = hi;
        *reinterpret_cast<uint32_t*>(Vl + ob + e) = lo;
    }
}

// ---------------------------------------------------------------------------
// Tensor-core flash attention (mma.sync bf16 hi/lo, exp2-domain softmax).
// MMA issue reordered into per-term passes (same trick as gemm_tc).
// ---------------------------------------------------------------------------
#define A_BK     64
#define A_PITCHB 272
#define A_QBYTES (128 * A_PITCHB)
#define A_KTILE  (A_BK * A_PITCHB)
#define A_STAGE  (4 * A_KTILE)
#define ATTN_SMEM (2 * A_QBYTES + 2 * A_STAGE)

__global__ __launch_bounds__(256)
void attn_tc(const __nv_bfloat16* __restrict__ Qh, const __nv_bfloat16* __restrict__ Ql,
             const __nv_bfloat16* __restrict__ Kh, const __nv_bfloat16* __restrict__ Kl,
             const __nv_bfloat16* __restrict__ Vh, const __nv_bfloat16* __restrict__ Vl,
             __nv_bfloat16* __restrict__ Oh, __nv_bfloat16* __restrict__ Ol)
{
    extern __shared__ char dsm[];
    const uint32_t base = smem_u32(dsm);
    const uint32_t sQh = base, sQl = base + A_QBYTES;
    const uint32_t stage0 = base + 2 * A_QBYTES;

    const int qb = blockIdx.x;
    const int h  = blockIdx.y;
    const int tid = threadIdx.x;
    const int warp = tid >> 5, lane = tid & 31;

    const __nv_bfloat16* kvsrc[4] = { Kh, Kl, Vh, Vl };

    {
        const size_t qoff = (size_t)(qb * 128) * DIM + h * DH;
#pragma unroll
        for (int g = 0; g < 8; ++g) {
            const int idx = tid + g * 256;
            const int row = idx >> 4, c = idx & 15;
            const size_t so = qoff + (size_t)row * DIM + c * 8;
            CP_ASYNC16(sQh + row * A_PITCHB + c * 16, Qh + so);
            CP_ASYNC16(sQl + row * A_PITCHB + c * 16, Ql + so);
        }
    }
    auto load_kv = [&](uint32_t st, int kt) {
        const size_t koff = (size_t)(kt * A_BK) * DIM + h * DH;
#pragma unroll
        for (int g = 0; g < 16; ++g) {
            const int t = g >> 2;
            const int idx = tid + (g & 3) * 256;
            const int row = idx >> 4, c = idx & 15;
            CP_ASYNC16(st + t * A_KTILE + row * A_PITCHB + c * 16,
                       kvsrc[t] + koff + (size_t)row * DIM + c * 8);
        }
    };

    load_kv(stage0, 0);
    CP_COMMIT();
    load_kv(stage0 + A_STAGE, 1);
    CP_COMMIT();

    float O[16][4];
#pragma unroll
    for (int i = 0; i < 16; i++)
#pragma unroll
        for (int j = 0; j < 4; j++) O[i][j] = 0.f;
    float m_run[2] = { -1e30f, -1e30f };
    float l_run[2] = { 0.f, 0.f };
    const float scale2 = 0.08838834764831845f * 1.4426950408889634f;

    constexpr int NT = S_LEN / A_BK;

    for (int kt = 0; kt < NT; ++kt) {
        if (kt == NT - 1) { CP_WAIT0(); } else { CP_WAIT1(); }
        __syncthreads();

        const uint32_t st = stage0 + (kt & 1) * A_STAGE;
        const uint32_t sKh = st, sKl = st + A_KTILE;
        const uint32_t sVh = st + 2 * A_KTILE, sVl = st + 3 * A_KTILE;

        // ---- S = Q K^T (16 x 64 per warp), 3-term split, per-term passes ----
        float sacc[8][4];
#pragma unroll
        for (int i = 0; i < 8; i++)
#pragma unroll
            for (int j = 0; j < 4; j++) sacc[i][j] = 0.f;

#pragma unroll
        for (int ks = 0; ks < 8; ++ks) {
            const uint32_t kb = ks * 32;
            uint32_t aH[4], aL[4];
            const uint32_t aro = (warp * 16 + (lane & 15)) * A_PITCHB
                                 + ((lane >> 4) * 16) + kb;
            LDMATRIX_X4(aH[0], aH[1], aH[2], aH[3], sQh + aro);
            LDMATRIX_X4(aL[0], aL[1], aL[2], aL[3], sQl + aro);
            uint32_t bH[4][4], bL[4][4];
#pragma unroll
            for (int nb = 0; nb < 4; ++nb) {
                const uint32_t bro = (nb * 16 + (lane & 7) + ((lane >> 4) << 3))
                                     * A_PITCHB + (((lane >> 3) & 1) * 16) + kb;
                LDMATRIX_X4(bH[nb][0], bH[nb][1], bH[nb][2], bH[nb][3], sKh + bro);
                LDMATRIX_X4(bL[nb][0], bL[nb][1], bL[nb][2], bL[nb][3], sKl + bro);
            }
            // pass hh (8 independent accumulators)
#pragma unroll
            for (int nb = 0; nb < 4; ++nb)
#pragma unroll
                for (int half = 0; half < 2; ++half) {
                    uint32_t b2[2] = { bH[nb][half * 2], bH[nb][half * 2 + 1] };
                    MMA_BF16(sacc[nb * 2 + half], aH, b2);
                }
            // pass hl
#pragma unroll
            for (int nb = 0; nb < 4; ++nb)
#pragma unroll
                for (int half = 0; half < 2; ++half) {
                    uint32_t b2[2] = { bL[nb][half * 2], bL[nb][half * 2 + 1] };
                    MMA_BF16(sacc[nb * 2 + half], aH, b2);
                }
            // pass lh
#pragma unroll
            for (int nb = 0; nb < 4; ++nb)
#pragma unroll
                for (int half = 0; half < 2; ++half) {
                    uint32_t b2[2] = { bH[nb][half * 2], bH[nb][half * 2 + 1] };
                    MMA_BF16(sacc[nb * 2 + half], aL, b2);
                }
        }

        // ---- online softmax in log2 domain ----
        float mt0 = -1e30f, mt1 = -1e30f;
#pragma unroll
        for (int f = 0; f < 8; ++f) {
            sacc[f][0] *= scale2; sacc[f][1] *= scale2;
            sacc[f][2] *= scale2; sacc[f][3] *= scale2;
            mt0 = fmaxf(mt0, fmaxf(sacc[f][0], sacc[f][1]));
            mt1 = fmaxf(mt1, fmaxf(sacc[f][2], sacc[f][3]));
        }
        mt0 = fmaxf(mt0, __shfl_xor_sync(0xffffffffu, mt0, 1));
        mt0 = fmaxf(mt0, __shfl_xor_sync(0xffffffffu, mt0, 2));
        mt1 = fmaxf(mt1, __shfl_xor_sync(0xffffffffu, mt1, 1));
        mt1 = fmaxf(mt1, __shfl_xor_sync(0xffffffffu, mt1, 2));
        const float mn0 = fmaxf(m_run[0], mt0), mn1 = fmaxf(m_run[1], mt1);
        const float al0 = fast_exp2(m_run[0] - mn0), al1 = fast_exp2(m_run[1] - mn1);
        m_run[0] = mn0; m_run[1] = mn1;

        float ls0 = 0.f, ls1 = 0.f;
#pragma unroll
        for (int f = 0; f < 8; ++f) {
            sacc[f][0] = fast_exp2(sacc[f][0] - mn0);
            sacc[f][1] = fast_exp2(sacc[f][1] - mn0);
            sacc[f][2] = fast_exp2(sacc[f][2] - mn1);
            sacc[f][3] = fast_exp2(sacc[f][3] - mn1);
            ls0 += sacc[f][0] + sacc[f][1];
            ls1 += sacc[f][2] + sacc[f][3];
        }
        ls0 += __shfl_xor_sync(0xffffffffu, ls0, 1);
        ls0 += __shfl_xor_sync(0xffffffffu, ls0, 2);
        ls1 += __shfl_xor_sync(0xffffffffu, ls1, 1);
        ls1 += __shfl_xor_sync(0xffffffffu, ls1, 2);
        l_run[0] = l_run[0] * al0 + ls0;
        l_run[1] = l_run[1] * al1 + ls1;

#pragma unroll
        for (int i = 0; i < 16; i++) {
            O[i][0] *= al0; O[i][1] *= al0;
            O[i][2] *= al1; O[i][3] *= al1;
        }

        // P accum-frags -> A-operand frags (hi/lo)
        uint32_t pH[4][4], pL[4][4];
#pragma unroll
        for (int j = 0; j < 4; ++j) {
            split2(sacc[2 * j][0],     sacc[2 * j][1],     pH[j][0], pL[j][0]);
            split2(sacc[2 * j][2],     sacc[2 * j][3],     pH[j][1], pL[j][1]);
            split2(sacc[2 * j + 1][0], sacc[2 * j + 1][1], pH[j][2], pL[j][2]);
            split2(sacc[2 * j + 1][2], sacc[2 * j + 1][3], pH[j][3], pL[j][3]);
        }

        // ---- O += P V (V via ldmatrix.trans), 3-term split, per-term passes ----
#pragma unroll
        for (int ks = 0; ks < 4; ++ks) {
            const uint32_t krow = ks * 16 + (lane & 7) + (((lane >> 3) & 1) * 8);
            uint32_t bH[8][4], bL[8][4];
#pragma unroll
            for (int nb = 0; nb < 8; ++nb) {
                const uint32_t ro = krow * A_PITCHB + nb * 32 + ((lane >> 4) * 16);
                LDMATRIX_X4_T(bH[nb][0], bH[nb][1], bH[nb][2], bH[nb][3], sVh + ro);
                LDMATRIX_X4_T(bL[nb][0], bL[nb][1], bL[nb][2], bL[nb][3], sVl + ro);
            }
            // pass hh (16 independent accumulators)
#pragma unroll
            for (int nb = 0; nb < 8; ++nb)
#pragma unroll
                for (int half = 0; half < 2; ++half) {
                    uint32_t b2[2] = { bH[nb][half * 2], bH[nb][half * 2 + 1] };
                    MMA_BF16(O[nb * 2 + half], pH[ks], b2);
                }
            // pass hl
#pragma unroll
            for (int nb = 0; nb < 8; ++nb)
#pragma unroll
                for (int half = 0; half < 2; ++half) {
                    uint32_t b2[2] = { bL[nb][half * 2], bL[nb][half * 2 + 1] };
                    MMA_BF16(O[nb * 2 + half], pH[ks], b2);
                }
            // pass lh
#pragma unroll
            for (int nb = 0; nb < 8; ++nb)
#pragma unroll
                for (int half = 0; half < 2; ++half) {
                    uint32_t b2[2] = { bH[nb][half * 2], bH[nb][half * 2 + 1] };
                    MMA_BF16(O[nb * 2 + half], pL[ks], b2);
                }
        }

        __syncthreads();
        if (kt + 2 < NT) {
            load_kv(stage0 + (kt & 1) * A_STAGE, kt + 2);
            CP_COMMIT();
        }
    }

    // ---- epilogue: write bf16 hi/lo operands for out-proj GEMM ----
    const float inv0 = 1.f / l_run[0], inv1 = 1.f / l_run[1];
    const int s0 = qb * 128 + warp * 16 + (lane >> 2);
#pragma unroll
    for (int nf = 0; nf < 16; ++nf) {
        const int col = h * DH + nf * 8 + (lane & 3) * 2;
        uint32_t hi, lo;
        split2(O[nf][0] * inv0, O[nf][1] * inv0, hi, lo);
        *reinterpret_cast<uint32_t*>(Oh + (size_t)s0 * DIM + col) = hi;
        *reinterpret_cast<uint32_t*>(Ol + (size_t)s0 * DIM + col) = lo;
        split2(O[nf][2] * inv1, O[nf][3] * inv1, hi, lo);
        *reinterpret_cast<uint32_t*>(Oh + (size_t)(s0 + 8) * DIM + col) = hi;
        *reinterpret_cast<uint32_t*>(Ol + (size_t)(s0 + 8) * DIM + col) = lo;
    }
}

// ---------------------------------------------------------------------------
// Launch
// ---------------------------------------------------------------------------
extern "C" void kernel_launch(void* const* d_in, const int* in_sizes, int n_in,
                              void* d_out, int out_size)
{
    const float* hidden = (const float*)d_in[0];
    const float* cos_t  = (const float*)d_in[1];
    const float* sin_t  = (const float*)d_in[2];
    const float* w_qkv  = (const float*)d_in[3];
    const float* b_qkv  = (const float*)d_in[4];
    const float* w_qn   = (const float*)d_in[5];
    const float* w_kn   = (const float*)d_in[6];
    const float* w_out  = (const float*)d_in[7];
    const float* b_out  = (const float*)d_in[8];
    float* out = (float*)d_out;

    float* qkv;
    __nv_bfloat16 *Ah, *Al, *Wqh, *Wql, *Woh, *Wol, *Qh, *Ql, *Kh, *Kl, *Vh, *Vl;
    cudaGetSymbolAddress((void**)&qkv, g_qkv);
    cudaGetSymbolAddress((void**)&Ah, g_Ah);
    cudaGetSymbolAddress((void**)&Al, g_Al);
    cudaGetSymbolAddress((void**)&Wqh, g_Wqkv_h);
    cudaGetSymbolAddress((void**)&Wql, g_Wqkv_l);
    cudaGetSymbolAddress((void**)&Woh, g_Wout_h);
    cudaGetSymbolAddress((void**)&Wol, g_Wout_l);
    cudaGetSymbolAddress((void**)&Qh, g_Qh);
    cudaGetSymbolAddress((void**)&Ql, g_Ql);
    cudaGetSymbolAddress((void**)&Kh, g_Kh);
    cudaGetSymbolAddress((void**)&Kl, g_Kl);
    cudaGetSymbolAddress((void**)&Vh, g_Vh);
    cudaGetSymbolAddress((void**)&Vl, g_Vl);

    cudaFuncSetAttribute(gemm_tc, cudaFuncAttributeMaxDynamicSharedMemorySize,
                         GEMM_SMEM);
    cudaFuncSetAttribute(attn_tc, cudaFuncAttributeMaxDynamicSharedMemorySize,
                         ATTN_SMEM);

    // Prepass: weight transpose+split, activation split
    transpose_split<<<dim3(DIM / 32, N3 / 32), 256>>>(w_qkv, Wqh, Wql, DIM, N3);
    transpose_split<<<dim3(DIM / 32, DIM / 32), 256>>>(w_out, Woh, Wol, DIM, DIM);
    split_rows<<<(S_LEN * DIM) / 1024, 256>>>(hidden, Ah, Al);

    // 1) QKV = X @ Wqkv + b (tensor cores)
    gemm_tc<<<dim3(S_LEN / 128, N3 / 128), 256, GEMM_SMEM>>>(
        Ah, Al, Wqh, Wql, b_qkv, qkv, N3);

    // 2) RMSNorm + RoPE + split q,k,v to bf16 hi/lo
    rmsnorm_rope_split<<<S_LEN, 256>>>(qkv, cos_t, sin_t, w_qn, w_kn,
                                       Qh, Ql, Kh, Kl, Vh, Vl);

    // 3) Tensor-core flash attention (emits bf16 hi/lo directly into Ah/Al)
    attn_tc<<<dim3(S_LEN / 128, NH), 256, ATTN_SMEM>>>(Qh, Ql, Kh, Kl, Vh, Vl, Ah, Al);

    // 4) out = attn_out @ Wout + b (tensor cores)
    gemm_tc<<<dim3(S_LEN / 128, DIM / 128), 256, GEMM_SMEM>>>(
        Ah, Al, Woh, Wol, b_out, out, DIM);
}